// round 10
// baseline (speedup 1.0000x reference)
#include <cuda_runtime.h>
#include <math.h>
#include <stdint.h>

#define N_NODES 30000
#define E_EDGES 480000
#define G_DIM   256
#define ATT_SCALE 0.0625f   /* 256^-0.5 */
#define LOG2E   1.4426950408889634f
#define LN_EPS  1e-5f

// ---------------- device scratch (static allocation only) ----------------
__device__ float g_x[N_NODES * G_DIM];   // normalized input
__device__ float g_q[N_NODES * G_DIM];
__device__ float g_k[N_NODES * G_DIM];
__device__ float g_v[N_NODES * G_DIM];
__device__ int   g_deg[N_NODES];
__device__ int   g_cur[N_NODES];
__device__ int   g_off[N_NODES + 1];
__device__ int   g_csr_src[E_EDGES];
__device__ int   g_bsum[32];

// ---------------- zero g_deg (separate so hist can be launch #2) ----------------
__global__ void zero_kernel() {
    int i = blockIdx.x * blockDim.x + threadIdx.x;
    if (i < N_NODES) g_deg[i] = 0;
}

// ---------------- CSR histogram ----------------
__global__ void hist_kernel(const int* __restrict__ dst) {
    int e = blockIdx.x * blockDim.x + threadIdx.x;
    if (e < E_EDGES) atomicAdd(&g_deg[dst[e]], 1);
}

// ---------------- LayerNorm (stats + apply), one warp per row ----------------
__global__ void ln_kernel(const float* __restrict__ s,
                          const float* __restrict__ gamma,
                          const float* __restrict__ beta) {
    int gtid = blockIdx.x * blockDim.x + threadIdx.x;
    int row = gtid >> 5;
    if (row >= N_NODES) return;
    int lane = threadIdx.x & 31;

    const float4* p = (const float4*)(s + (size_t)row * G_DIM);
    float4 f0 = p[lane];
    float4 f1 = p[lane + 32];
    float sum = f0.x + f0.y + f0.z + f0.w + f1.x + f1.y + f1.z + f1.w;
    float sq  = f0.x*f0.x + f0.y*f0.y + f0.z*f0.z + f0.w*f0.w
              + f1.x*f1.x + f1.y*f1.y + f1.z*f1.z + f1.w*f1.w;
    #pragma unroll
    for (int o = 16; o > 0; o >>= 1) {
        sum += __shfl_xor_sync(0xffffffffu, sum, o);
        sq  += __shfl_xor_sync(0xffffffffu, sq, o);
    }
    float mu = sum * (1.f / G_DIM);
    float rs = rsqrtf(sq * (1.f / G_DIM) - mu * mu + LN_EPS);

    float4 ga = ((const float4*)gamma)[lane];
    float4 gb = ((const float4*)gamma)[lane + 32];
    float4 ba = ((const float4*)beta)[lane];
    float4 bb = ((const float4*)beta)[lane + 32];
    float4 o0, o1;
    o0.x = (f0.x - mu) * rs * ga.x + ba.x;
    o0.y = (f0.y - mu) * rs * ga.y + ba.y;
    o0.z = (f0.z - mu) * rs * ga.z + ba.z;
    o0.w = (f0.w - mu) * rs * ga.w + ba.w;
    o1.x = (f1.x - mu) * rs * gb.x + bb.x;
    o1.y = (f1.y - mu) * rs * gb.y + bb.y;
    o1.z = (f1.z - mu) * rs * gb.z + bb.z;
    o1.w = (f1.w - mu) * rs * gb.w + bb.w;
    float4* op = (float4*)(g_x + (size_t)row * G_DIM);
    op[lane]      = o0;
    op[lane + 32] = o1;
}

// ---------------- tf32 mma (raw fp32 bits; HW truncates mantissa) ----------------
__device__ __forceinline__ void mma_tf32(float c[4], const uint32_t a[4], const uint32_t b[2]) {
    asm volatile(
        "mma.sync.aligned.m16n8k8.row.col.f32.tf32.tf32.f32 "
        "{%0,%1,%2,%3}, {%4,%5,%6,%7}, {%8,%9}, {%0,%1,%2,%3};"
        : "+f"(c[0]), "+f"(c[1]), "+f"(c[2]), "+f"(c[3])
        : "r"(a[0]), "r"(a[1]), "r"(a[2]), "r"(a[3]), "r"(b[0]), "r"(b[1]));
}

// ---------------- QKV GEMM (tf32, double-buffered smem, 1 sync/K-tile) ----------------
__global__ __launch_bounds__(256) void qkv_gemm_tf32_kernel(
    const float* __restrict__ W) {

    __shared__ uint32_t Asm[2][4][8][32][4];   // 2 x 16 KB
    __shared__ uint32_t Bsm[2][4][8][32][2];   // 2 x  8 KB  (total 48 KB)

    int tid  = threadIdx.x;
    int warp = tid >> 5;
    int lane = tid & 31;
    int wm = warp >> 1;
    int wn = warp & 1;
    int bm = blockIdx.y * 128;
    int bn = blockIdx.x * 64;

    float acc[2][4][4];
    #pragma unroll
    for (int mi = 0; mi < 2; mi++)
        #pragma unroll
        for (int ni = 0; ni < 4; ni++)
            #pragma unroll
            for (int r = 0; r < 4; r++) acc[mi][ni][r] = 0.f;

    int ar[4], ac4[4];
    #pragma unroll
    for (int i = 0; i < 4; i++) {
        int idx = tid + i * 256;
        ar[i]  = idx >> 3;
        ac4[i] = (idx & 7) * 4;
    }
    int br[2], bc4[2];
    #pragma unroll
    for (int i = 0; i < 2; i++) {
        int idx = tid + i * 256;
        br[i]  = idx >> 4;
        bc4[i] = (idx & 15) * 4;
    }

    float4 pa[4], pb[2];
    #pragma unroll
    for (int i = 0; i < 4; i++) {
        int gr = bm + ar[i];
        pa[i] = (gr < N_NODES) ? *(const float4*)(g_x + (size_t)gr * G_DIM + ac4[i])
                               : make_float4(0.f, 0.f, 0.f, 0.f);
    }
    #pragma unroll
    for (int i = 0; i < 2; i++)
        pb[i] = *(const float4*)(W + (size_t)br[i] * 768 + bn + bc4[i]);

    #pragma unroll
    for (int i = 0; i < 4; i++) {
        float fv[4] = {pa[i].x, pa[i].y, pa[i].z, pa[i].w};
        int mi = ar[i] >> 4, rr = ar[i] & 15;
        #pragma unroll
        for (int j = 0; j < 4; j++) {
            int col = ac4[i] + j;
            int ks = col >> 3, cc = col & 7;
            int lt = (rr & 7) * 4 + (cc & 3);
            int rg = ((rr >> 3) & 1) | ((cc >> 2) << 1);
            Asm[0][ks][mi][lt][rg] = __float_as_uint(fv[j]);
        }
    }
    #pragma unroll
    for (int i = 0; i < 2; i++) {
        float fv[4] = {pb[i].x, pb[i].y, pb[i].z, pb[i].w};
        int ks = br[i] >> 3, kk = br[i] & 7;
        #pragma unroll
        for (int j = 0; j < 4; j++) {
            int col = bc4[i] + j;
            int ni = col >> 3, nn = col & 7;
            int lt = nn * 4 + (kk & 3);
            int rg = kk >> 2;
            Bsm[0][ks][ni][lt][rg] = __float_as_uint(fv[j]);
        }
    }
    __syncthreads();

    for (int kt8 = 0; kt8 < 8; kt8++) {
        int cur = kt8 & 1;
        if (kt8 < 7) {
            int kt = (kt8 + 1) * 32;
            #pragma unroll
            for (int i = 0; i < 4; i++) {
                int gr = bm + ar[i];
                pa[i] = (gr < N_NODES)
                      ? *(const float4*)(g_x + (size_t)gr * G_DIM + kt + ac4[i])
                      : make_float4(0.f, 0.f, 0.f, 0.f);
            }
            #pragma unroll
            for (int i = 0; i < 2; i++)
                pb[i] = *(const float4*)(W + (size_t)(kt + br[i]) * 768 + bn + bc4[i]);
        }

        #pragma unroll
        for (int ks = 0; ks < 4; ks++) {
            uint32_t a[2][4];
            #pragma unroll
            for (int mi = 0; mi < 2; mi++)
                *(uint4*)a[mi] = *(const uint4*)&Asm[cur][ks][wm * 2 + mi][lane][0];
            uint32_t b[4][2];
            #pragma unroll
            for (int ni = 0; ni < 4; ni++)
                *(uint2*)b[ni] = *(const uint2*)&Bsm[cur][ks][wn * 4 + ni][lane][0];
            #pragma unroll
            for (int mi = 0; mi < 2; mi++)
                #pragma unroll
                for (int ni = 0; ni < 4; ni++)
                    mma_tf32(acc[mi][ni], a[mi], b[ni]);
        }

        if (kt8 < 7) {
            int nxt = cur ^ 1;
            #pragma unroll
            for (int i = 0; i < 4; i++) {
                float fv[4] = {pa[i].x, pa[i].y, pa[i].z, pa[i].w};
                int mi = ar[i] >> 4, rr = ar[i] & 15;
                #pragma unroll
                for (int j = 0; j < 4; j++) {
                    int col = ac4[i] + j;
                    int ks = col >> 3, cc = col & 7;
                    int lt = (rr & 7) * 4 + (cc & 3);
                    int rg = ((rr >> 3) & 1) | ((cc >> 2) << 1);
                    Asm[nxt][ks][mi][lt][rg] = __float_as_uint(fv[j]);
                }
            }
            #pragma unroll
            for (int i = 0; i < 2; i++) {
                float fv[4] = {pb[i].x, pb[i].y, pb[i].z, pb[i].w};
                int ks = br[i] >> 3, kk = br[i] & 7;
                #pragma unroll
                for (int j = 0; j < 4; j++) {
                    int col = bc4[i] + j;
                    int ni = col >> 3, nn = col & 7;
                    int lt = nn * 4 + (kk & 3);
                    int rg = kk >> 2;
                    Bsm[nxt][ks][ni][lt][rg] = __float_as_uint(fv[j]);
                }
            }
            __syncthreads();
        }
    }

    int third = bn >> 8;
    float* outp = (third == 0) ? g_q : (third == 1) ? g_k : g_v;
    int lc_base = (bn & 255) + wn * 32;
    int gid = lane >> 2, tig = lane & 3;
    #pragma unroll
    for (int mi = 0; mi < 2; mi++) {
        int row0 = bm + wm * 32 + mi * 16 + gid;
        #pragma unroll
        for (int ni = 0; ni < 4; ni++) {
            int col = lc_base + ni * 8 + tig * 2;
            if (row0 < N_NODES)
                *(float2*)&outp[(size_t)row0 * G_DIM + col] =
                    make_float2(acc[mi][ni][0], acc[mi][ni][1]);
            if (row0 + 8 < N_NODES)
                *(float2*)&outp[(size_t)(row0 + 8) * G_DIM + col] =
                    make_float2(acc[mi][ni][2], acc[mi][ni][3]);
        }
    }
}

// ---------------- scan ----------------
__global__ __launch_bounds__(1024) void scan_phase1() {
    __shared__ int ws[32];
    int t = threadIdx.x;
    int lane = t & 31, wid = t >> 5;
    int idx = blockIdx.x * 1024 + t;
    int v = (idx < N_NODES) ? g_deg[idx] : 0;

    int x = v;
    #pragma unroll
    for (int o = 1; o < 32; o <<= 1) {
        int y = __shfl_up_sync(0xffffffffu, x, o);
        if (lane >= o) x += y;
    }
    if (lane == 31) ws[wid] = x;
    __syncthreads();
    if (wid == 0) {
        int w = ws[lane];
        #pragma unroll
        for (int o = 1; o < 32; o <<= 1) {
            int y = __shfl_up_sync(0xffffffffu, w, o);
            if (lane >= o) w += y;
        }
        ws[lane] = w;
    }
    __syncthreads();
    int ex = x - v + ((wid > 0) ? ws[wid - 1] : 0);
    if (idx < N_NODES) { g_off[idx] = ex; g_cur[idx] = 0; }
    if (t == 1023) g_bsum[blockIdx.x] = ex + v;
}

__global__ void scan_phase2() {
    int t = threadIdx.x;   // 32 threads
    int v = (t < 30) ? g_bsum[t] : 0;
    int x = v;
    #pragma unroll
    for (int o = 1; o < 32; o <<= 1) {
        int y = __shfl_up_sync(0xffffffffu, x, o);
        if (t >= o) x += y;
    }
    g_bsum[t] = x - v;
}

__global__ __launch_bounds__(1024) void scan_phase3() {
    int idx = blockIdx.x * 1024 + threadIdx.x;
    if (idx < N_NODES) g_off[idx] += g_bsum[blockIdx.x];
    if (idx == 0) g_off[N_NODES] = E_EDGES;
}

__global__ void scatter_kernel(const int* __restrict__ src, const int* __restrict__ dst) {
    int e = blockIdx.x * blockDim.x + threadIdx.x;
    if (e >= E_EDGES) return;
    int d = dst[e];
    int pos = atomicAdd(&g_cur[d], 1);
    g_csr_src[g_off[d] + pos] = src[e];
}

// ---------------- per-node attention: 64 threads (2 warps) per dst node ----------------
__device__ __forceinline__ float ex2f(float x) {
    float r;
    asm("ex2.approx.ftz.f32 %0, %1;" : "=f"(r) : "f"(x));
    return r;
}

__global__ __launch_bounds__(256) void attn_kernel(float* __restrict__ out) {
    int gtid = blockIdx.x * blockDim.x + threadIdx.x;
    int node = gtid >> 6;
    if (node >= N_NODES) return;
    int doff = gtid & 63;     // float4 index within the 256-dim row

    const float KS = ATT_SCALE * LOG2E;
    float4 kv = ((const float4*)(g_k + (size_t)node * G_DIM))[doff];
    kv.x *= KS; kv.y *= KS; kv.z *= KS; kv.w *= KS;

    float4 z = make_float4(0.f, 0.f, 0.f, 0.f);
    float4 a = make_float4(0.f, 0.f, 0.f, 0.f);

    int e   = g_off[node];
    int end = g_off[node + 1];

    for (; e + 4 <= end; e += 4) {
        int s0 = g_csr_src[e];
        int s1 = g_csr_src[e + 1];
        int s2 = g_csr_src[e + 2];
        int s3 = g_csr_src[e + 3];
        float4 q0 = ((const float4*)(g_q + (size_t)s0 * G_DIM))[doff];
        float4 v0 = ((const float4*)(g_v + (size_t)s0 * G_DIM))[doff];
        float4 q1 = ((const float4*)(g_q + (size_t)s1 * G_DIM))[doff];
        float4 v1 = ((const float4*)(g_v + (size_t)s1 * G_DIM))[doff];
        float4 q2 = ((const float4*)(g_q + (size_t)s2 * G_DIM))[doff];
        float4 v2 = ((const float4*)(g_v + (size_t)s2 * G_DIM))[doff];
        float4 q3 = ((const float4*)(g_q + (size_t)s3 * G_DIM))[doff];
        float4 v3 = ((const float4*)(g_v + (size_t)s3 * G_DIM))[doff];

        float p;
        p = ex2f(q0.x * kv.x); z.x += p; a.x = fmaf(p, v0.x, a.x);
        p = ex2f(q0.y * kv.y); z.y += p; a.y = fmaf(p, v0.y, a.y);
        p = ex2f(q0.z * kv.z); z.z += p; a.z = fmaf(p, v0.z, a.z);
        p = ex2f(q0.w * kv.w); z.w += p; a.w = fmaf(p, v0.w, a.w);
        p = ex2f(q1.x * kv.x); z.x += p; a.x = fmaf(p, v1.x, a.x);
        p = ex2f(q1.y * kv.y); z.y += p; a.y = fmaf(p, v1.y, a.y);
        p = ex2f(q1.z * kv.z); z.z += p; a.z = fmaf(p, v1.z, a.z);
        p = ex2f(q1.w * kv.w); z.w += p; a.w = fmaf(p, v1.w, a.w);
        p = ex2f(q2.x * kv.x); z.x += p; a.x = fmaf(p, v2.x, a.x);
        p = ex2f(q2.y * kv.y); z.y += p; a.y = fmaf(p, v2.y, a.y);
        p = ex2f(q2.z * kv.z); z.z += p; a.z = fmaf(p, v2.z, a.z);
        p = ex2f(q2.w * kv.w); z.w += p; a.w = fmaf(p, v2.w, a.w);
        p = ex2f(q3.x * kv.x); z.x += p; a.x = fmaf(p, v3.x, a.x);
        p = ex2f(q3.y * kv.y); z.y += p; a.y = fmaf(p, v3.y, a.y);
        p = ex2f(q3.z * kv.z); z.z += p; a.z = fmaf(p, v3.z, a.z);
        p = ex2f(q3.w * kv.w); z.w += p; a.w = fmaf(p, v3.w, a.w);
    }
    for (; e < end; e++) {
        int s0 = g_csr_src[e];
        float4 q0 = ((const float4*)(g_q + (size_t)s0 * G_DIM))[doff];
        float4 v0 = ((const float4*)(g_v + (size_t)s0 * G_DIM))[doff];
        float p;
        p = ex2f(q0.x * kv.x); z.x += p; a.x = fmaf(p, v0.x, a.x);
        p = ex2f(q0.y * kv.y); z.y += p; a.y = fmaf(p, v0.y, a.y);
        p = ex2f(q0.z * kv.z); z.z += p; a.z = fmaf(p, v0.z, a.z);
        p = ex2f(q0.w * kv.w); z.w += p; a.w = fmaf(p, v0.w, a.w);
    }

    float4 r;
    r.x = (z.x > 0.f) ? a.x / z.x : 0.f;
    r.y = (z.y > 0.f) ? a.y / z.y : 0.f;
    r.z = (z.z > 0.f) ? a.z / z.z : 0.f;
    r.w = (z.w > 0.f) ? a.w / z.w : 0.f;
    ((float4*)(out + (size_t)node * G_DIM))[doff] = r;
}

// ---------------- launch ----------------
// Order chosen so the GEMM is the 4th launch (ncu's -s capture window):
// zero(1), hist(2), ln(3), gemm(4), scan1(5), scan2(6), scan3(7), scatter(8), attn(9)
extern "C" void kernel_launch(void* const* d_in, const int* in_sizes, int n_in,
                              void* d_out, int out_size) {
    const float* s     = (const float*)d_in[0];
    const float* Wqkv  = (const float*)d_in[1];
    const float* gamma = (const float*)d_in[2];
    const float* beta  = (const float*)d_in[3];
    const int*   src   = (const int*)d_in[4];
    const int*   dst   = (const int*)d_in[5];
    float* out = (float*)d_out;

    zero_kernel<<<(N_NODES + 255) / 256, 256>>>();
    hist_kernel<<<(E_EDGES + 255) / 256, 256>>>(dst);
    ln_kernel<<<(N_NODES * 32 + 255) / 256, 256>>>(s, gamma, beta);

    dim3 gemm_grid(768 / 64, (N_NODES + 127) / 128);
    qkv_gemm_tf32_kernel<<<gemm_grid, 256>>>(Wqkv);

    const int SCAN_BLOCKS = (N_NODES + 1023) / 1024;   // 30
    scan_phase1<<<SCAN_BLOCKS, 1024>>>();
    scan_phase2<<<1, 32>>>();
    scan_phase3<<<SCAN_BLOCKS, 1024>>>();

    scatter_kernel<<<(E_EDGES + 255) / 256, 256>>>(src, dst);

    attn_kernel<<<(N_NODES * 64 + 255) / 256, 256>>>(out);
}

// round 12
// speedup vs baseline: 1.0963x; 1.0963x over previous
#include <cuda_runtime.h>
#include <math.h>
#include <stdint.h>

#define N_NODES 30000
#define E_EDGES 480000
#define G_DIM   256
#define ATT_SCALE 0.0625f   /* 256^-0.5 */
#define LOG2E   1.4426950408889634f
#define LN_EPS  1e-5f

// padded smem strides (words) — break store bank conflicts
#define A_KS_STRIDE 1028                    /* 1024 + 4: ks stride ≡ 4 mod 32 */
#define A_BUF_STRIDE (4 * A_KS_STRIDE)      /* 4112 */
#define B_NI_STRIDE 68                      /* 64 + 4: ni stride ≡ 4 mod 32 */
#define B_KS_STRIDE (8 * B_NI_STRIDE)       /* 544 */
#define B_BUF_STRIDE (4 * B_KS_STRIDE)      /* 2176 */
#define GEMM_SMEM_BYTES ((2 * A_BUF_STRIDE + 2 * B_BUF_STRIDE) * 4)  /* 50304 */

// ---------------- device scratch (static allocation only) ----------------
__device__ float g_x[N_NODES * G_DIM];   // normalized input
__device__ float g_q[N_NODES * G_DIM];
__device__ float g_k[N_NODES * G_DIM];
__device__ float g_v[N_NODES * G_DIM];
__device__ int   g_deg[N_NODES];
__device__ int   g_cur[N_NODES];
__device__ int   g_off[N_NODES + 1];
__device__ int   g_csr_src[E_EDGES];
__device__ int   g_bsum[32];

// ---------------- zero g_deg ----------------
__global__ void zero_kernel() {
    int i = blockIdx.x * blockDim.x + threadIdx.x;
    if (i < N_NODES) g_deg[i] = 0;
}

// ---------------- CSR histogram ----------------
__global__ void hist_kernel(const int* __restrict__ dst) {
    int e = blockIdx.x * blockDim.x + threadIdx.x;
    if (e < E_EDGES) atomicAdd(&g_deg[dst[e]], 1);
}

// ---------------- LayerNorm (stats + apply), one warp per row ----------------
__global__ void ln_kernel(const float* __restrict__ s,
                          const float* __restrict__ gamma,
                          const float* __restrict__ beta) {
    int gtid = blockIdx.x * blockDim.x + threadIdx.x;
    int row = gtid >> 5;
    if (row >= N_NODES) return;
    int lane = threadIdx.x & 31;

    const float4* p = (const float4*)(s + (size_t)row * G_DIM);
    float4 f0 = p[lane];
    float4 f1 = p[lane + 32];
    float sum = f0.x + f0.y + f0.z + f0.w + f1.x + f1.y + f1.z + f1.w;
    float sq  = f0.x*f0.x + f0.y*f0.y + f0.z*f0.z + f0.w*f0.w
              + f1.x*f1.x + f1.y*f1.y + f1.z*f1.z + f1.w*f1.w;
    #pragma unroll
    for (int o = 16; o > 0; o >>= 1) {
        sum += __shfl_xor_sync(0xffffffffu, sum, o);
        sq  += __shfl_xor_sync(0xffffffffu, sq, o);
    }
    float mu = sum * (1.f / G_DIM);
    float rs = rsqrtf(sq * (1.f / G_DIM) - mu * mu + LN_EPS);

    float4 ga = ((const float4*)gamma)[lane];
    float4 gb = ((const float4*)gamma)[lane + 32];
    float4 ba = ((const float4*)beta)[lane];
    float4 bb = ((const float4*)beta)[lane + 32];
    float4 o0, o1;
    o0.x = (f0.x - mu) * rs * ga.x + ba.x;
    o0.y = (f0.y - mu) * rs * ga.y + ba.y;
    o0.z = (f0.z - mu) * rs * ga.z + ba.z;
    o0.w = (f0.w - mu) * rs * ga.w + ba.w;
    o1.x = (f1.x - mu) * rs * gb.x + bb.x;
    o1.y = (f1.y - mu) * rs * gb.y + bb.y;
    o1.z = (f1.z - mu) * rs * gb.z + bb.z;
    o1.w = (f1.w - mu) * rs * gb.w + bb.w;
    float4* op = (float4*)(g_x + (size_t)row * G_DIM);
    op[lane]      = o0;
    op[lane + 32] = o1;
}

// ---------------- tf32 helpers ----------------
__device__ __forceinline__ uint32_t to_tf32(float x) {
    uint32_t t;
    asm("cvt.rna.tf32.f32 %0, %1;" : "=r"(t) : "f"(x));
    return t;
}

__device__ __forceinline__ void mma_tf32(float c[4], const uint32_t a[4], const uint32_t b[2]) {
    asm volatile(
        "mma.sync.aligned.m16n8k8.row.col.f32.tf32.tf32.f32 "
        "{%0,%1,%2,%3}, {%4,%5,%6,%7}, {%8,%9}, {%0,%1,%2,%3};"
        : "+f"(c[0]), "+f"(c[1]), "+f"(c[2]), "+f"(c[3])
        : "r"(a[0]), "r"(a[1]), "r"(a[2]), "r"(a[3]), "r"(b[0]), "r"(b[1]));
}

// ---------------- QKV GEMM (tf32, double-buffered padded smem) ----------------
// C[N,768] = X[N,256] @ W[256,768]; block tile 128x64, K-chunk 32, 8 warps (4Mx2N).
__global__ __launch_bounds__(256) void qkv_gemm_tf32_kernel(
    const float* __restrict__ W) {

    extern __shared__ uint32_t smem[];
    uint32_t* As = smem;                          // 2 * A_BUF_STRIDE words
    uint32_t* Bs = smem + 2 * A_BUF_STRIDE;       // 2 * B_BUF_STRIDE words

    int tid  = threadIdx.x;
    int warp = tid >> 5;
    int lane = tid & 31;
    int wm = warp >> 1;
    int wn = warp & 1;
    int bm = blockIdx.y * 128;
    int bn = blockIdx.x * 64;

    float acc[2][4][4];
    #pragma unroll
    for (int mi = 0; mi < 2; mi++)
        #pragma unroll
        for (int ni = 0; ni < 4; ni++)
            #pragma unroll
            for (int r = 0; r < 4; r++) acc[mi][ni][r] = 0.f;

    int ar[4], ac4[4];
    #pragma unroll
    for (int i = 0; i < 4; i++) {
        int idx = tid + i * 256;
        ar[i]  = idx >> 3;
        ac4[i] = (idx & 7) * 4;
    }
    int br[2], bc4[2];
    #pragma unroll
    for (int i = 0; i < 2; i++) {
        int idx = tid + i * 256;
        br[i]  = idx >> 4;
        bc4[i] = (idx & 15) * 4;
    }

    float4 pa[4], pb[2];
    #pragma unroll
    for (int i = 0; i < 4; i++) {
        int gr = bm + ar[i];
        pa[i] = (gr < N_NODES) ? *(const float4*)(g_x + (size_t)gr * G_DIM + ac4[i])
                               : make_float4(0.f, 0.f, 0.f, 0.f);
    }
    #pragma unroll
    for (int i = 0; i < 2; i++)
        pb[i] = *(const float4*)(W + (size_t)br[i] * 768 + bn + bc4[i]);

    // stage K-tile 0 into buffer 0
    #pragma unroll
    for (int i = 0; i < 4; i++) {
        float fv[4] = {pa[i].x, pa[i].y, pa[i].z, pa[i].w};
        int mi = ar[i] >> 4, rr = ar[i] & 15;
        #pragma unroll
        for (int j = 0; j < 4; j++) {
            int col = ac4[i] + j;
            int ks = col >> 3, cc = col & 7;
            int lt = (rr & 7) * 4 + (cc & 3);
            int rg = ((rr >> 3) & 1) | ((cc >> 2) << 1);
            As[ks * A_KS_STRIDE + mi * 128 + lt * 4 + rg] = to_tf32(fv[j]);
        }
    }
    #pragma unroll
    for (int i = 0; i < 2; i++) {
        float fv[4] = {pb[i].x, pb[i].y, pb[i].z, pb[i].w};
        int ks = br[i] >> 3, kk = br[i] & 7;
        #pragma unroll
        for (int j = 0; j < 4; j++) {
            int col = bc4[i] + j;
            int ni = col >> 3, nn = col & 7;
            int lt = nn * 4 + (kk & 3);
            int rg = kk >> 2;
            Bs[ks * B_KS_STRIDE + ni * B_NI_STRIDE + lt * 2 + rg] = to_tf32(fv[j]);
        }
    }
    __syncthreads();

    for (int kt8 = 0; kt8 < 8; kt8++) {
        int cur = kt8 & 1;
        uint32_t* Ac = As + cur * A_BUF_STRIDE;
        uint32_t* Bc = Bs + cur * B_BUF_STRIDE;

        if (kt8 < 7) {
            int kt = (kt8 + 1) * 32;
            #pragma unroll
            for (int i = 0; i < 4; i++) {
                int gr = bm + ar[i];
                pa[i] = (gr < N_NODES)
                      ? *(const float4*)(g_x + (size_t)gr * G_DIM + kt + ac4[i])
                      : make_float4(0.f, 0.f, 0.f, 0.f);
            }
            #pragma unroll
            for (int i = 0; i < 2; i++)
                pb[i] = *(const float4*)(W + (size_t)(kt + br[i]) * 768 + bn + bc4[i]);
        }

        #pragma unroll
        for (int ks = 0; ks < 4; ks++) {
            uint32_t a[2][4];
            #pragma unroll
            for (int mi = 0; mi < 2; mi++)
                *(uint4*)a[mi] = *(const uint4*)&Ac[ks * A_KS_STRIDE + (wm * 2 + mi) * 128 + lane * 4];
            uint32_t b[4][2];
            #pragma unroll
            for (int ni = 0; ni < 4; ni++)
                *(uint2*)b[ni] = *(const uint2*)&Bc[ks * B_KS_STRIDE + (wn * 4 + ni) * B_NI_STRIDE + lane * 2];
            #pragma unroll
            for (int mi = 0; mi < 2; mi++)
                #pragma unroll
                for (int ni = 0; ni < 4; ni++)
                    mma_tf32(acc[mi][ni], a[mi], b[ni]);
        }

        if (kt8 < 7) {
            uint32_t* An = As + (cur ^ 1) * A_BUF_STRIDE;
            uint32_t* Bn = Bs + (cur ^ 1) * B_BUF_STRIDE;
            #pragma unroll
            for (int i = 0; i < 4; i++) {
                float fv[4] = {pa[i].x, pa[i].y, pa[i].z, pa[i].w};
                int mi = ar[i] >> 4, rr = ar[i] & 15;
                #pragma unroll
                for (int j = 0; j < 4; j++) {
                    int col = ac4[i] + j;
                    int ks = col >> 3, cc = col & 7;
                    int lt = (rr & 7) * 4 + (cc & 3);
                    int rg = ((rr >> 3) & 1) | ((cc >> 2) << 1);
                    An[ks * A_KS_STRIDE + mi * 128 + lt * 4 + rg] = to_tf32(fv[j]);
                }
            }
            #pragma unroll
            for (int i = 0; i < 2; i++) {
                float fv[4] = {pb[i].x, pb[i].y, pb[i].z, pb[i].w};
                int ks = br[i] >> 3, kk = br[i] & 7;
                #pragma unroll
                for (int j = 0; j < 4; j++) {
                    int col = bc4[i] + j;
                    int ni = col >> 3, nn = col & 7;
                    int lt = nn * 4 + (kk & 3);
                    int rg = kk >> 2;
                    Bn[ks * B_KS_STRIDE + ni * B_NI_STRIDE + lt * 2 + rg] = to_tf32(fv[j]);
                }
            }
            __syncthreads();
        }
    }

    int third = bn >> 8;
    float* outp = (third == 0) ? g_q : (third == 1) ? g_k : g_v;
    int lc_base = (bn & 255) + wn * 32;
    int gid = lane >> 2, tig = lane & 3;
    #pragma unroll
    for (int mi = 0; mi < 2; mi++) {
        int row0 = bm + wm * 32 + mi * 16 + gid;
        #pragma unroll
        for (int ni = 0; ni < 4; ni++) {
            int col = lc_base + ni * 8 + tig * 2;
            if (row0 < N_NODES)
                *(float2*)&outp[(size_t)row0 * G_DIM + col] =
                    make_float2(acc[mi][ni][0], acc[mi][ni][1]);
            if (row0 + 8 < N_NODES)
                *(float2*)&outp[(size_t)(row0 + 8) * G_DIM + col] =
                    make_float2(acc[mi][ni][2], acc[mi][ni][3]);
        }
    }
}

// ---------------- scan ----------------
__global__ __launch_bounds__(1024) void scan_phase1() {
    __shared__ int ws[32];
    int t = threadIdx.x;
    int lane = t & 31, wid = t >> 5;
    int idx = blockIdx.x * 1024 + t;
    int v = (idx < N_NODES) ? g_deg[idx] : 0;

    int x = v;
    #pragma unroll
    for (int o = 1; o < 32; o <<= 1) {
        int y = __shfl_up_sync(0xffffffffu, x, o);
        if (lane >= o) x += y;
    }
    if (lane == 31) ws[wid] = x;
    __syncthreads();
    if (wid == 0) {
        int w = ws[lane];
        #pragma unroll
        for (int o = 1; o < 32; o <<= 1) {
            int y = __shfl_up_sync(0xffffffffu, w, o);
            if (lane >= o) w += y;
        }
        ws[lane] = w;
    }
    __syncthreads();
    int ex = x - v + ((wid > 0) ? ws[wid - 1] : 0);
    if (idx < N_NODES) { g_off[idx] = ex; g_cur[idx] = 0; }
    if (t == 1023) g_bsum[blockIdx.x] = ex + v;
}

__global__ void scan_phase2() {
    int t = threadIdx.x;   // 32 threads
    int v = (t < 30) ? g_bsum[t] : 0;
    int x = v;
    #pragma unroll
    for (int o = 1; o < 32; o <<= 1) {
        int y = __shfl_up_sync(0xffffffffu, x, o);
        if (t >= o) x += y;
    }
    g_bsum[t] = x - v;
}

__global__ __launch_bounds__(1024) void scan_phase3() {
    int idx = blockIdx.x * 1024 + threadIdx.x;
    if (idx < N_NODES) g_off[idx] += g_bsum[blockIdx.x];
    if (idx == 0) g_off[N_NODES] = E_EDGES;
}

__global__ void scatter_kernel(const int* __restrict__ src, const int* __restrict__ dst) {
    int e = blockIdx.x * blockDim.x + threadIdx.x;
    if (e >= E_EDGES) return;
    int d = dst[e];
    int pos = atomicAdd(&g_cur[d], 1);
    g_csr_src[g_off[d] + pos] = src[e];
}

// ---------------- per-node attention: 64 threads (2 warps) per dst node ----------------
__device__ __forceinline__ float ex2f(float x) {
    float r;
    asm("ex2.approx.ftz.f32 %0, %1;" : "=f"(r) : "f"(x));
    return r;
}

__global__ __launch_bounds__(256) void attn_kernel(float* __restrict__ out) {
    int gtid = blockIdx.x * blockDim.x + threadIdx.x;
    int node = gtid >> 6;
    if (node >= N_NODES) return;
    int doff = gtid & 63;     // float4 index within the 256-dim row

    const float KS = ATT_SCALE * LOG2E;
    float4 kv = ((const float4*)(g_k + (size_t)node * G_DIM))[doff];
    kv.x *= KS; kv.y *= KS; kv.z *= KS; kv.w *= KS;

    float4 z = make_float4(0.f, 0.f, 0.f, 0.f);
    float4 a = make_float4(0.f, 0.f, 0.f, 0.f);

    int e   = g_off[node];
    int end = g_off[node + 1];

    for (; e + 4 <= end; e += 4) {
        int s0 = g_csr_src[e];
        int s1 = g_csr_src[e + 1];
        int s2 = g_csr_src[e + 2];
        int s3 = g_csr_src[e + 3];
        float4 q0 = ((const float4*)(g_q + (size_t)s0 * G_DIM))[doff];
        float4 v0 = ((const float4*)(g_v + (size_t)s0 * G_DIM))[doff];
        float4 q1 = ((const float4*)(g_q + (size_t)s1 * G_DIM))[doff];
        float4 v1 = ((const float4*)(g_v + (size_t)s1 * G_DIM))[doff];
        float4 q2 = ((const float4*)(g_q + (size_t)s2 * G_DIM))[doff];
        float4 v2 = ((const float4*)(g_v + (size_t)s2 * G_DIM))[doff];
        float4 q3 = ((const float4*)(g_q + (size_t)s3 * G_DIM))[doff];
        float4 v3 = ((const float4*)(g_v + (size_t)s3 * G_DIM))[doff];

        float p;
        p = ex2f(q0.x * kv.x); z.x += p; a.x = fmaf(p, v0.x, a.x);
        p = ex2f(q0.y * kv.y); z.y += p; a.y = fmaf(p, v0.y, a.y);
        p = ex2f(q0.z * kv.z); z.z += p; a.z = fmaf(p, v0.z, a.z);
        p = ex2f(q0.w * kv.w); z.w += p; a.w = fmaf(p, v0.w, a.w);
        p = ex2f(q1.x * kv.x); z.x += p; a.x = fmaf(p, v1.x, a.x);
        p = ex2f(q1.y * kv.y); z.y += p; a.y = fmaf(p, v1.y, a.y);
        p = ex2f(q1.z * kv.z); z.z += p; a.z = fmaf(p, v1.z, a.z);
        p = ex2f(q1.w * kv.w); z.w += p; a.w = fmaf(p, v1.w, a.w);
        p = ex2f(q2.x * kv.x); z.x += p; a.x = fmaf(p, v2.x, a.x);
        p = ex2f(q2.y * kv.y); z.y += p; a.y = fmaf(p, v2.y, a.y);
        p = ex2f(q2.z * kv.z); z.z += p; a.z = fmaf(p, v2.z, a.z);
        p = ex2f(q2.w * kv.w); z.w += p; a.w = fmaf(p, v2.w, a.w);
        p = ex2f(q3.x * kv.x); z.x += p; a.x = fmaf(p, v3.x, a.x);
        p = ex2f(q3.y * kv.y); z.y += p; a.y = fmaf(p, v3.y, a.y);
        p = ex2f(q3.z * kv.z); z.z += p; a.z = fmaf(p, v3.z, a.z);
        p = ex2f(q3.w * kv.w); z.w += p; a.w = fmaf(p, v3.w, a.w);
    }
    for (; e < end; e++) {
        int s0 = g_csr_src[e];
        float4 q0 = ((const float4*)(g_q + (size_t)s0 * G_DIM))[doff];
        float4 v0 = ((const float4*)(g_v + (size_t)s0 * G_DIM))[doff];
        float p;
        p = ex2f(q0.x * kv.x); z.x += p; a.x = fmaf(p, v0.x, a.x);
        p = ex2f(q0.y * kv.y); z.y += p; a.y = fmaf(p, v0.y, a.y);
        p = ex2f(q0.z * kv.z); z.z += p; a.z = fmaf(p, v0.z, a.z);
        p = ex2f(q0.w * kv.w); z.w += p; a.w = fmaf(p, v0.w, a.w);
    }

    float4 r;
    r.x = (z.x > 0.f) ? a.x / z.x : 0.f;
    r.y = (z.y > 0.f) ? a.y / z.y : 0.f;
    r.z = (z.z > 0.f) ? a.z / z.z : 0.f;
    r.w = (z.w > 0.f) ? a.w / z.w : 0.f;
    ((float4*)(out + (size_t)node * G_DIM))[doff] = r;
}

// ---------------- launch ----------------
// Order keeps the GEMM as the 4th launch (ncu -s capture window):
// zero(1), hist(2), ln(3), gemm(4), scan1(5), scan2(6), scan3(7), scatter(8), attn(9)
extern "C" void kernel_launch(void* const* d_in, const int* in_sizes, int n_in,
                              void* d_out, int out_size) {
    const float* s     = (const float*)d_in[0];
    const float* Wqkv  = (const float*)d_in[1];
    const float* gamma = (const float*)d_in[2];
    const float* beta  = (const float*)d_in[3];
    const int*   src   = (const int*)d_in[4];
    const int*   dst   = (const int*)d_in[5];
    float* out = (float*)d_out;

    static int smem_cfg_done = 0;
    if (!smem_cfg_done) {
        cudaFuncSetAttribute(qkv_gemm_tf32_kernel,
                             cudaFuncAttributeMaxDynamicSharedMemorySize,
                             GEMM_SMEM_BYTES);
        smem_cfg_done = 1;
    }

    zero_kernel<<<(N_NODES + 255) / 256, 256>>>();
    hist_kernel<<<(E_EDGES + 255) / 256, 256>>>(dst);
    ln_kernel<<<(N_NODES * 32 + 255) / 256, 256>>>(s, gamma, beta);

    dim3 gemm_grid(768 / 64, (N_NODES + 127) / 128);
    qkv_gemm_tf32_kernel<<<gemm_grid, 256, GEMM_SMEM_BYTES>>>(Wqkv);

    const int SCAN_BLOCKS = (N_NODES + 1023) / 1024;   // 30
    scan_phase1<<<SCAN_BLOCKS, 1024>>>();
    scan_phase2<<<1, 32>>>();
    scan_phase3<<<SCAN_BLOCKS, 1024>>>();

    scatter_kernel<<<(E_EDGES + 255) / 256, 256>>>(src, dst);

    attn_kernel<<<(N_NODES * 64 + 255) / 256, 256>>>(out);
}

// round 13
// speedup vs baseline: 1.1094x; 1.0119x over previous
#include <cuda_runtime.h>
#include <math.h>
#include <stdint.h>

#define N_NODES 30000
#define E_EDGES 480000
#define G_DIM   256
#define ATT_SCALE 0.0625f   /* 256^-0.5 */
#define LOG2E   1.4426950408889634f
#define LN_EPS  1e-5f

// natural-layout smem tiles (word strides chosen for conflict-free access)
#define A_ROW_STRIDE 36                    /* 32 cols + 4 pad  (≡4 mod 32) */
#define A_BUF (128 * A_ROW_STRIDE)         /* 4608 words */
#define B_ROW_STRIDE 72                    /* 64 cols + 8 pad  (≡8 mod 32) */
#define B_BUF (32 * B_ROW_STRIDE)          /* 2304 words */
#define GEMM_SMEM_BYTES ((2 * A_BUF + 2 * B_BUF) * 4)   /* 55296 */

// ---------------- device scratch (static allocation only) ----------------
__device__ float g_x[N_NODES * G_DIM];   // normalized input
__device__ float g_q[N_NODES * G_DIM];
__device__ float g_k[N_NODES * G_DIM];
__device__ float g_v[N_NODES * G_DIM];
__device__ int   g_deg[N_NODES];
__device__ int   g_cur[N_NODES];
__device__ int   g_off[N_NODES + 1];
__device__ int   g_csr_src[E_EDGES];
__device__ int   g_bsum[32];

// ---------------- zero g_deg ----------------
__global__ void zero_kernel() {
    int i = blockIdx.x * blockDim.x + threadIdx.x;
    if (i < N_NODES) g_deg[i] = 0;
}

// ---------------- CSR histogram ----------------
__global__ void hist_kernel(const int* __restrict__ dst) {
    int e = blockIdx.x * blockDim.x + threadIdx.x;
    if (e < E_EDGES) atomicAdd(&g_deg[dst[e]], 1);
}

// ---------------- LayerNorm (stats + apply), one warp per row ----------------
__global__ void ln_kernel(const float* __restrict__ s,
                          const float* __restrict__ gamma,
                          const float* __restrict__ beta) {
    int gtid = blockIdx.x * blockDim.x + threadIdx.x;
    int row = gtid >> 5;
    if (row >= N_NODES) return;
    int lane = threadIdx.x & 31;

    const float4* p = (const float4*)(s + (size_t)row * G_DIM);
    float4 f0 = p[lane];
    float4 f1 = p[lane + 32];
    float sum = f0.x + f0.y + f0.z + f0.w + f1.x + f1.y + f1.z + f1.w;
    float sq  = f0.x*f0.x + f0.y*f0.y + f0.z*f0.z + f0.w*f0.w
              + f1.x*f1.x + f1.y*f1.y + f1.z*f1.z + f1.w*f1.w;
    #pragma unroll
    for (int o = 16; o > 0; o >>= 1) {
        sum += __shfl_xor_sync(0xffffffffu, sum, o);
        sq  += __shfl_xor_sync(0xffffffffu, sq, o);
    }
    float mu = sum * (1.f / G_DIM);
    float rs = rsqrtf(sq * (1.f / G_DIM) - mu * mu + LN_EPS);

    float4 ga = ((const float4*)gamma)[lane];
    float4 gb = ((const float4*)gamma)[lane + 32];
    float4 ba = ((const float4*)beta)[lane];
    float4 bb = ((const float4*)beta)[lane + 32];
    float4 o0, o1;
    o0.x = (f0.x - mu) * rs * ga.x + ba.x;
    o0.y = (f0.y - mu) * rs * ga.y + ba.y;
    o0.z = (f0.z - mu) * rs * ga.z + ba.z;
    o0.w = (f0.w - mu) * rs * ga.w + ba.w;
    o1.x = (f1.x - mu) * rs * gb.x + bb.x;
    o1.y = (f1.y - mu) * rs * gb.y + bb.y;
    o1.z = (f1.z - mu) * rs * gb.z + bb.z;
    o1.w = (f1.w - mu) * rs * gb.w + bb.w;
    float4* op = (float4*)(g_x + (size_t)row * G_DIM);
    op[lane]      = o0;
    op[lane + 32] = o1;
}

// ---------------- tf32 helpers ----------------
__device__ __forceinline__ uint32_t to_tf32(float x) {
    uint32_t t;
    asm("cvt.rna.tf32.f32 %0, %1;" : "=r"(t) : "f"(x));
    return t;
}

__device__ __forceinline__ void mma_tf32(float c[4], const uint32_t a[4], const uint32_t b[2]) {
    asm volatile(
        "mma.sync.aligned.m16n8k8.row.col.f32.tf32.tf32.f32 "
        "{%0,%1,%2,%3}, {%4,%5,%6,%7}, {%8,%9}, {%0,%1,%2,%3};"
        : "+f"(c[0]), "+f"(c[1]), "+f"(c[2]), "+f"(c[3])
        : "r"(a[0]), "r"(a[1]), "r"(a[2]), "r"(a[3]), "r"(b[0]), "r"(b[1]));
}

// ---------------- QKV GEMM (tf32, natural-layout smem, double-buffered) ----------------
// C[N,768] = X[N,256] @ W[256,768]; block tile 128x64, K-chunk 32, 8 warps (4Mx2N).
// A tile: [128 rows][36 words]; B tile: [32 k-rows][72 words]. Staging = STS.128
// at crossbar minimum; fragment loads = conflict-free LDS.32 at mma coordinates.
__global__ __launch_bounds__(256) void qkv_gemm_tf32_kernel(
    const float* __restrict__ W) {

    extern __shared__ uint32_t smem[];
    uint32_t* As = smem;                    // 2 x A_BUF
    uint32_t* Bs = smem + 2 * A_BUF;        // 2 x B_BUF

    int tid  = threadIdx.x;
    int warp = tid >> 5;
    int lane = tid & 31;
    int wm = warp >> 1;
    int wn = warp & 1;
    int bm = blockIdx.y * 128;
    int bn = blockIdx.x * 64;

    float acc[2][4][4];
    #pragma unroll
    for (int mi = 0; mi < 2; mi++)
        #pragma unroll
        for (int ni = 0; ni < 4; ni++)
            #pragma unroll
            for (int r = 0; r < 4; r++) acc[mi][ni][r] = 0.f;

    // staging coordinates (loop-invariant)
    int ar[4], ac4[4], a_st[4];
    #pragma unroll
    for (int i = 0; i < 4; i++) {
        int idx = tid + i * 256;
        ar[i]  = idx >> 3;
        ac4[i] = (idx & 7) * 4;
        a_st[i] = ar[i] * A_ROW_STRIDE + ac4[i];
    }
    int br[2], bc4[2], b_st[2];
    #pragma unroll
    for (int i = 0; i < 2; i++) {
        int idx = tid + i * 256;
        br[i]  = idx >> 4;
        bc4[i] = (idx & 15) * 4;
        b_st[i] = br[i] * B_ROW_STRIDE + bc4[i];
    }

    // fragment-load base offsets (rest are compile-time immediates)
    int a_ld = (wm * 32 + (lane >> 2)) * A_ROW_STRIDE + (lane & 3);
    int b_ld = (lane & 3) * B_ROW_STRIDE + wn * 32 + (lane >> 2);

    float4 pa[4], pb[2];
    #pragma unroll
    for (int i = 0; i < 4; i++) {
        int gr = bm + ar[i];
        pa[i] = (gr < N_NODES) ? *(const float4*)(g_x + (size_t)gr * G_DIM + ac4[i])
                               : make_float4(0.f, 0.f, 0.f, 0.f);
    }
    #pragma unroll
    for (int i = 0; i < 2; i++)
        pb[i] = *(const float4*)(W + (size_t)br[i] * 768 + bn + bc4[i]);

    // stage K-tile 0 into buffer 0 (vectorized STS.128)
    #pragma unroll
    for (int i = 0; i < 4; i++)
        *(uint4*)&As[a_st[i]] = make_uint4(to_tf32(pa[i].x), to_tf32(pa[i].y),
                                           to_tf32(pa[i].z), to_tf32(pa[i].w));
    #pragma unroll
    for (int i = 0; i < 2; i++)
        *(uint4*)&Bs[b_st[i]] = make_uint4(to_tf32(pb[i].x), to_tf32(pb[i].y),
                                           to_tf32(pb[i].z), to_tf32(pb[i].w));
    __syncthreads();

    for (int kt8 = 0; kt8 < 8; kt8++) {
        int cur = kt8 & 1;
        const uint32_t* Ac = As + cur * A_BUF;
        const uint32_t* Bc = Bs + cur * B_BUF;

        if (kt8 < 7) {
            int kt = (kt8 + 1) * 32;
            #pragma unroll
            for (int i = 0; i < 4; i++) {
                int gr = bm + ar[i];
                pa[i] = (gr < N_NODES)
                      ? *(const float4*)(g_x + (size_t)gr * G_DIM + kt + ac4[i])
                      : make_float4(0.f, 0.f, 0.f, 0.f);
            }
            #pragma unroll
            for (int i = 0; i < 2; i++)
                pb[i] = *(const float4*)(W + (size_t)(kt + br[i]) * 768 + bn + bc4[i]);
        }

        #pragma unroll
        for (int ks = 0; ks < 4; ks++) {
            // A fragments: a0=(r,c) a1=(r+8,c) a2=(r,c+4) a3=(r+8,c+4)
            uint32_t a[2][4];
            #pragma unroll
            for (int mi = 0; mi < 2; mi++) {
                int base = a_ld + mi * (16 * A_ROW_STRIDE) + ks * 8;
                a[mi][0] = Ac[base];
                a[mi][1] = Ac[base + 8 * A_ROW_STRIDE];
                a[mi][2] = Ac[base + 4];
                a[mi][3] = Ac[base + 8 * A_ROW_STRIDE + 4];
            }
            // B fragments: b0=(k,n) b1=(k+4,n)
            uint32_t b[4][2];
            #pragma unroll
            for (int ni = 0; ni < 4; ni++) {
                int base = b_ld + ks * (8 * B_ROW_STRIDE) + ni * 8;
                b[ni][0] = Bc[base];
                b[ni][1] = Bc[base + 4 * B_ROW_STRIDE];
            }
            #pragma unroll
            for (int mi = 0; mi < 2; mi++)
                #pragma unroll
                for (int ni = 0; ni < 4; ni++)
                    mma_tf32(acc[mi][ni], a[mi], b[ni]);
        }

        if (kt8 < 7) {
            uint32_t* An = As + (cur ^ 1) * A_BUF;
            uint32_t* Bn = Bs + (cur ^ 1) * B_BUF;
            #pragma unroll
            for (int i = 0; i < 4; i++)
                *(uint4*)&An[a_st[i]] = make_uint4(to_tf32(pa[i].x), to_tf32(pa[i].y),
                                                   to_tf32(pa[i].z), to_tf32(pa[i].w));
            #pragma unroll
            for (int i = 0; i < 2; i++)
                *(uint4*)&Bn[b_st[i]] = make_uint4(to_tf32(pb[i].x), to_tf32(pb[i].y),
                                                   to_tf32(pb[i].z), to_tf32(pb[i].w));
            __syncthreads();
        }
    }

    int third = bn >> 8;
    float* outp = (third == 0) ? g_q : (third == 1) ? g_k : g_v;
    int lc_base = (bn & 255) + wn * 32;
    int gid = lane >> 2, tig = lane & 3;
    #pragma unroll
    for (int mi = 0; mi < 2; mi++) {
        int row0 = bm + wm * 32 + mi * 16 + gid;
        #pragma unroll
        for (int ni = 0; ni < 4; ni++) {
            int col = lc_base + ni * 8 + tig * 2;
            if (row0 < N_NODES)
                *(float2*)&outp[(size_t)row0 * G_DIM + col] =
                    make_float2(acc[mi][ni][0], acc[mi][ni][1]);
            if (row0 + 8 < N_NODES)
                *(float2*)&outp[(size_t)(row0 + 8) * G_DIM + col] =
                    make_float2(acc[mi][ni][2], acc[mi][ni][3]);
        }
    }
}

// ---------------- scan ----------------
__global__ __launch_bounds__(1024) void scan_phase1() {
    __shared__ int ws[32];
    int t = threadIdx.x;
    int lane = t & 31, wid = t >> 5;
    int idx = blockIdx.x * 1024 + t;
    int v = (idx < N_NODES) ? g_deg[idx] : 0;

    int x = v;
    #pragma unroll
    for (int o = 1; o < 32; o <<= 1) {
        int y = __shfl_up_sync(0xffffffffu, x, o);
        if (lane >= o) x += y;
    }
    if (lane == 31) ws[wid] = x;
    __syncthreads();
    if (wid == 0) {
        int w = ws[lane];
        #pragma unroll
        for (int o = 1; o < 32; o <<= 1) {
            int y = __shfl_up_sync(0xffffffffu, w, o);
            if (lane >= o) w += y;
        }
        ws[lane] = w;
    }
    __syncthreads();
    int ex = x - v + ((wid > 0) ? ws[wid - 1] : 0);
    if (idx < N_NODES) { g_off[idx] = ex; g_cur[idx] = 0; }
    if (t == 1023) g_bsum[blockIdx.x] = ex + v;
}

__global__ void scan_phase2() {
    int t = threadIdx.x;   // 32 threads
    int v = (t < 30) ? g_bsum[t] : 0;
    int x = v;
    #pragma unroll
    for (int o = 1; o < 32; o <<= 1) {
        int y = __shfl_up_sync(0xffffffffu, x, o);
        if (t >= o) x += y;
    }
    g_bsum[t] = x - v;
}

__global__ __launch_bounds__(1024) void scan_phase3() {
    int idx = blockIdx.x * 1024 + threadIdx.x;
    if (idx < N_NODES) g_off[idx] += g_bsum[blockIdx.x];
    if (idx == 0) g_off[N_NODES] = E_EDGES;
}

__global__ void scatter_kernel(const int* __restrict__ src, const int* __restrict__ dst) {
    int e = blockIdx.x * blockDim.x + threadIdx.x;
    if (e >= E_EDGES) return;
    int d = dst[e];
    int pos = atomicAdd(&g_cur[d], 1);
    g_csr_src[g_off[d] + pos] = src[e];
}

// ---------------- per-node attention: 64 threads (2 warps) per dst node ----------------
__device__ __forceinline__ float ex2f(float x) {
    float r;
    asm("ex2.approx.ftz.f32 %0, %1;" : "=f"(r) : "f"(x));
    return r;
}

__global__ __launch_bounds__(256) void attn_kernel(float* __restrict__ out) {
    int gtid = blockIdx.x * blockDim.x + threadIdx.x;
    int node = gtid >> 6;
    if (node >= N_NODES) return;
    int doff = gtid & 63;     // float4 index within the 256-dim row

    const float KS = ATT_SCALE * LOG2E;
    float4 kv = ((const float4*)(g_k + (size_t)node * G_DIM))[doff];
    kv.x *= KS; kv.y *= KS; kv.z *= KS; kv.w *= KS;

    float4 z = make_float4(0.f, 0.f, 0.f, 0.f);
    float4 a = make_float4(0.f, 0.f, 0.f, 0.f);

    int e   = g_off[node];
    int end = g_off[node + 1];

    for (; e + 4 <= end; e += 4) {
        int s0 = g_csr_src[e];
        int s1 = g_csr_src[e + 1];
        int s2 = g_csr_src[e + 2];
        int s3 = g_csr_src[e + 3];
        float4 q0 = ((const float4*)(g_q + (size_t)s0 * G_DIM))[doff];
        float4 v0 = ((const float4*)(g_v + (size_t)s0 * G_DIM))[doff];
        float4 q1 = ((const float4*)(g_q + (size_t)s1 * G_DIM))[doff];
        float4 v1 = ((const float4*)(g_v + (size_t)s1 * G_DIM))[doff];
        float4 q2 = ((const float4*)(g_q + (size_t)s2 * G_DIM))[doff];
        float4 v2 = ((const float4*)(g_v + (size_t)s2 * G_DIM))[doff];
        float4 q3 = ((const float4*)(g_q + (size_t)s3 * G_DIM))[doff];
        float4 v3 = ((const float4*)(g_v + (size_t)s3 * G_DIM))[doff];

        float p;
        p = ex2f(q0.x * kv.x); z.x += p; a.x = fmaf(p, v0.x, a.x);
        p = ex2f(q0.y * kv.y); z.y += p; a.y = fmaf(p, v0.y, a.y);
        p = ex2f(q0.z * kv.z); z.z += p; a.z = fmaf(p, v0.z, a.z);
        p = ex2f(q0.w * kv.w); z.w += p; a.w = fmaf(p, v0.w, a.w);
        p = ex2f(q1.x * kv.x); z.x += p; a.x = fmaf(p, v1.x, a.x);
        p = ex2f(q1.y * kv.y); z.y += p; a.y = fmaf(p, v1.y, a.y);
        p = ex2f(q1.z * kv.z); z.z += p; a.z = fmaf(p, v1.z, a.z);
        p = ex2f(q1.w * kv.w); z.w += p; a.w = fmaf(p, v1.w, a.w);
        p = ex2f(q2.x * kv.x); z.x += p; a.x = fmaf(p, v2.x, a.x);
        p = ex2f(q2.y * kv.y); z.y += p; a.y = fmaf(p, v2.y, a.y);
        p = ex2f(q2.z * kv.z); z.z += p; a.z = fmaf(p, v2.z, a.z);
        p = ex2f(q2.w * kv.w); z.w += p; a.w = fmaf(p, v2.w, a.w);
        p = ex2f(q3.x * kv.x); z.x += p; a.x = fmaf(p, v3.x, a.x);
        p = ex2f(q3.y * kv.y); z.y += p; a.y = fmaf(p, v3.y, a.y);
        p = ex2f(q3.z * kv.z); z.z += p; a.z = fmaf(p, v3.z, a.z);
        p = ex2f(q3.w * kv.w); z.w += p; a.w = fmaf(p, v3.w, a.w);
    }
    for (; e < end; e++) {
        int s0 = g_csr_src[e];
        float4 q0 = ((const float4*)(g_q + (size_t)s0 * G_DIM))[doff];
        float4 v0 = ((const float4*)(g_v + (size_t)s0 * G_DIM))[doff];
        float p;
        p = ex2f(q0.x * kv.x); z.x += p; a.x = fmaf(p, v0.x, a.x);
        p = ex2f(q0.y * kv.y); z.y += p; a.y = fmaf(p, v0.y, a.y);
        p = ex2f(q0.z * kv.z); z.z += p; a.z = fmaf(p, v0.z, a.z);
        p = ex2f(q0.w * kv.w); z.w += p; a.w = fmaf(p, v0.w, a.w);
    }

    float4 r;
    r.x = (z.x > 0.f) ? a.x / z.x : 0.f;
    r.y = (z.y > 0.f) ? a.y / z.y : 0.f;
    r.z = (z.z > 0.f) ? a.z / z.z : 0.f;
    r.w = (z.w > 0.f) ? a.w / z.w : 0.f;
    ((float4*)(out + (size_t)node * G_DIM))[doff] = r;
}

// ---------------- launch ----------------
// Order keeps the GEMM as the 4th launch (ncu -s capture window):
// zero(1), hist(2), ln(3), gemm(4), scan1(5), scan2(6), scan3(7), scatter(8), attn(9)
extern "C" void kernel_launch(void* const* d_in, const int* in_sizes, int n_in,
                              void* d_out, int out_size) {
    const float* s     = (const float*)d_in[0];
    const float* Wqkv  = (const float*)d_in[1];
    const float* gamma = (const float*)d_in[2];
    const float* beta  = (const float*)d_in[3];
    const int*   src   = (const int*)d_in[4];
    const int*   dst   = (const int*)d_in[5];
    float* out = (float*)d_out;

    static int smem_cfg_done = 0;
    if (!smem_cfg_done) {
        cudaFuncSetAttribute(qkv_gemm_tf32_kernel,
                             cudaFuncAttributeMaxDynamicSharedMemorySize,
                             GEMM_SMEM_BYTES);
        smem_cfg_done = 1;
    }

    zero_kernel<<<(N_NODES + 255) / 256, 256>>>();
    hist_kernel<<<(E_EDGES + 255) / 256, 256>>>(dst);
    ln_kernel<<<(N_NODES * 32 + 255) / 256, 256>>>(s, gamma, beta);

    dim3 gemm_grid(768 / 64, (N_NODES + 127) / 128);
    qkv_gemm_tf32_kernel<<<gemm_grid, 256, GEMM_SMEM_BYTES>>>(Wqkv);

    const int SCAN_BLOCKS = (N_NODES + 1023) / 1024;   // 30
    scan_phase1<<<SCAN_BLOCKS, 1024>>>();
    scan_phase2<<<1, 32>>>();
    scan_phase3<<<SCAN_BLOCKS, 1024>>>();

    scatter_kernel<<<(E_EDGES + 255) / 256, 256>>>(src, dst);

    attn_kernel<<<(N_NODES * 64 + 255) / 256, 256>>>(out);
}

// round 14
// speedup vs baseline: 1.1645x; 1.0497x over previous
#include <cuda_runtime.h>
#include <math.h>
#include <stdint.h>

#define N_NODES 30000
#define E_EDGES 480000
#define G_DIM   256
#define ATT_SCALE 0.0625f   /* 256^-0.5 */
#define LOG2E   1.4426950408889634f
#define LN_EPS  1e-5f

// natural-layout smem tiles (word strides chosen for conflict-free access)
#define A_ROW_STRIDE 36                    /* 32 cols + 4 pad  (≡4 mod 32) */
#define A_BUF (128 * A_ROW_STRIDE)         /* 4608 words */
#define B_ROW_STRIDE 72                    /* 64 cols + 8 pad  (≡8 mod 32) */
#define B_BUF (32 * B_ROW_STRIDE)          /* 2304 words */
#define GEMM_SMEM_BYTES ((2 * A_BUF + 2 * B_BUF) * 4)   /* 55296 */

#define W_ELEMS (G_DIM * 768)              /* 196608 */
#define W_VEC4  (W_ELEMS / 4)              /* 49152 */

// ---------------- device scratch (static allocation only) ----------------
__device__ float    g_x[N_NODES * G_DIM];   // LN output, pre-rounded to tf32
__device__ uint32_t g_wt[W_ELEMS];          // W pre-rounded to tf32 bits
__device__ float    g_q[N_NODES * G_DIM];
__device__ float    g_k[N_NODES * G_DIM];
__device__ float    g_v[N_NODES * G_DIM];
__device__ int      g_deg[N_NODES];
__device__ int      g_cur[N_NODES];
__device__ int      g_off[N_NODES + 1];
__device__ int      g_csr_src[E_EDGES];
__device__ int      g_bsum[32];

// ---------------- tf32 helpers ----------------
__device__ __forceinline__ uint32_t to_tf32(float x) {
    uint32_t t;
    asm("cvt.rna.tf32.f32 %0, %1;" : "=r"(t) : "f"(x));
    return t;
}

__device__ __forceinline__ void mma_tf32(float c[4], const uint32_t a[4], const uint32_t b[2]) {
    asm volatile(
        "mma.sync.aligned.m16n8k8.row.col.f32.tf32.tf32.f32 "
        "{%0,%1,%2,%3}, {%4,%5,%6,%7}, {%8,%9}, {%0,%1,%2,%3};"
        : "+f"(c[0]), "+f"(c[1]), "+f"(c[2]), "+f"(c[3])
        : "r"(a[0]), "r"(a[1]), "r"(a[2]), "r"(a[3]), "r"(b[0]), "r"(b[1]));
}

__device__ __forceinline__ void ldsm_x4(uint32_t& r0, uint32_t& r1, uint32_t& r2,
                                        uint32_t& r3, uint32_t saddr) {
    asm volatile("ldmatrix.sync.aligned.m8n8.x4.shared.b16 {%0,%1,%2,%3}, [%4];"
                 : "=r"(r0), "=r"(r1), "=r"(r2), "=r"(r3) : "r"(saddr));
}

// ---------------- zero g_deg + pre-convert W to tf32 ----------------
__global__ void zero_wconv_kernel(const float* __restrict__ W) {
    int i = blockIdx.x * blockDim.x + threadIdx.x;
    if (i < N_NODES) g_deg[i] = 0;
    if (i < W_VEC4) {
        float4 f = ((const float4*)W)[i];
        ((uint4*)g_wt)[i] = make_uint4(to_tf32(f.x), to_tf32(f.y),
                                       to_tf32(f.z), to_tf32(f.w));
    }
}

// ---------------- CSR histogram ----------------
__global__ void hist_kernel(const int* __restrict__ dst) {
    int e = blockIdx.x * blockDim.x + threadIdx.x;
    if (e < E_EDGES) atomicAdd(&g_deg[dst[e]], 1);
}

// ---------------- LayerNorm (stats + apply + tf32 round), one warp per row ----------------
__global__ void ln_kernel(const float* __restrict__ s,
                          const float* __restrict__ gamma,
                          const float* __restrict__ beta) {
    int gtid = blockIdx.x * blockDim.x + threadIdx.x;
    int row = gtid >> 5;
    if (row >= N_NODES) return;
    int lane = threadIdx.x & 31;

    const float4* p = (const float4*)(s + (size_t)row * G_DIM);
    float4 f0 = p[lane];
    float4 f1 = p[lane + 32];
    float sum = f0.x + f0.y + f0.z + f0.w + f1.x + f1.y + f1.z + f1.w;
    float sq  = f0.x*f0.x + f0.y*f0.y + f0.z*f0.z + f0.w*f0.w
              + f1.x*f1.x + f1.y*f1.y + f1.z*f1.z + f1.w*f1.w;
    #pragma unroll
    for (int o = 16; o > 0; o >>= 1) {
        sum += __shfl_xor_sync(0xffffffffu, sum, o);
        sq  += __shfl_xor_sync(0xffffffffu, sq, o);
    }
    float mu = sum * (1.f / G_DIM);
    float rs = rsqrtf(sq * (1.f / G_DIM) - mu * mu + LN_EPS);

    float4 ga = ((const float4*)gamma)[lane];
    float4 gb = ((const float4*)gamma)[lane + 32];
    float4 ba = ((const float4*)beta)[lane];
    float4 bb = ((const float4*)beta)[lane + 32];
    float4 o0, o1;
    o0.x = __uint_as_float(to_tf32((f0.x - mu) * rs * ga.x + ba.x));
    o0.y = __uint_as_float(to_tf32((f0.y - mu) * rs * ga.y + ba.y));
    o0.z = __uint_as_float(to_tf32((f0.z - mu) * rs * ga.z + ba.z));
    o0.w = __uint_as_float(to_tf32((f0.w - mu) * rs * ga.w + ba.w));
    o1.x = __uint_as_float(to_tf32((f1.x - mu) * rs * gb.x + bb.x));
    o1.y = __uint_as_float(to_tf32((f1.y - mu) * rs * gb.y + bb.y));
    o1.z = __uint_as_float(to_tf32((f1.z - mu) * rs * gb.z + bb.z));
    o1.w = __uint_as_float(to_tf32((f1.w - mu) * rs * gb.w + bb.w));
    float4* op = (float4*)(g_x + (size_t)row * G_DIM);
    op[lane]      = o0;
    op[lane + 32] = o1;
}

// ---------------- QKV GEMM (tf32, natural smem, ldmatrix A, zero in-loop CVT) ----------------
// C[N,768] = X[N,256] @ W[256,768]; block tile 128x64, K-chunk 32, 8 warps (4Mx2N).
__global__ __launch_bounds__(256) void qkv_gemm_tf32_kernel() {

    extern __shared__ uint32_t smem[];
    uint32_t* As = smem;                    // 2 x A_BUF
    uint32_t* Bs = smem + 2 * A_BUF;        // 2 x B_BUF

    int tid  = threadIdx.x;
    int warp = tid >> 5;
    int lane = tid & 31;
    int wm = warp >> 1;
    int wn = warp & 1;
    int bm = blockIdx.y * 128;
    int bn = blockIdx.x * 64;

    float acc[2][4][4];
    #pragma unroll
    for (int mi = 0; mi < 2; mi++)
        #pragma unroll
        for (int ni = 0; ni < 4; ni++)
            #pragma unroll
            for (int r = 0; r < 4; r++) acc[mi][ni][r] = 0.f;

    // staging coordinates (loop-invariant)
    int ar[4], ac4[4], a_st[4];
    #pragma unroll
    for (int i = 0; i < 4; i++) {
        int idx = tid + i * 256;
        ar[i]  = idx >> 3;
        ac4[i] = (idx & 7) * 4;
        a_st[i] = ar[i] * A_ROW_STRIDE + ac4[i];
    }
    int br[2], bc4[2], b_st[2];
    #pragma unroll
    for (int i = 0; i < 2; i++) {
        int idx = tid + i * 256;
        br[i]  = idx >> 4;
        bc4[i] = (idx & 15) * 4;
        b_st[i] = br[i] * B_ROW_STRIDE + bc4[i];
    }

    // ldmatrix per-lane row addresses for A (byte, shared space)
    // x4 tiles: t0=(r,c) t1=(r+8,c) t2=(r,c+4) t3=(r+8,c+4) -> a0..a3
    uint32_t smem_sh = (uint32_t)__cvta_generic_to_shared(smem);
    int lr = lane & 7, tile = lane >> 3;
    int a_row = wm * 32 + (tile & 1) * 8 + lr;
    int a_colw = (tile >> 1) * 4;
    uint32_t a_sm0 = smem_sh + (uint32_t)(a_row * A_ROW_STRIDE + a_colw) * 4u;

    // B fragment LDS offsets (conflict-free: 8*(l&3) + (l>>2) is a bijection mod 32)
    int b_ld = (lane & 3) * B_ROW_STRIDE + wn * 32 + (lane >> 2);

    uint4 pa[4], pb[2];
    #pragma unroll
    for (int i = 0; i < 4; i++) {
        int gr = bm + ar[i];
        pa[i] = (gr < N_NODES) ? *(const uint4*)(g_x + (size_t)gr * G_DIM + ac4[i])
                               : make_uint4(0u, 0u, 0u, 0u);
    }
    #pragma unroll
    for (int i = 0; i < 2; i++)
        pb[i] = *(const uint4*)&g_wt[br[i] * 768 + bn + bc4[i]];

    // stage K-tile 0 into buffer 0 (pure bit-copy STS.128)
    #pragma unroll
    for (int i = 0; i < 4; i++) *(uint4*)&As[a_st[i]] = pa[i];
    #pragma unroll
    for (int i = 0; i < 2; i++) *(uint4*)&Bs[b_st[i]] = pb[i];
    __syncthreads();

    for (int kt8 = 0; kt8 < 8; kt8++) {
        int cur = kt8 & 1;
        const uint32_t* Bc = Bs + cur * B_BUF;
        uint32_t a_base = a_sm0 + (uint32_t)(cur * A_BUF) * 4u;

        if (kt8 < 7) {
            int kt = (kt8 + 1) * 32;
            #pragma unroll
            for (int i = 0; i < 4; i++) {
                int gr = bm + ar[i];
                pa[i] = (gr < N_NODES)
                      ? *(const uint4*)(g_x + (size_t)gr * G_DIM + kt + ac4[i])
                      : make_uint4(0u, 0u, 0u, 0u);
            }
            #pragma unroll
            for (int i = 0; i < 2; i++)
                pb[i] = *(const uint4*)&g_wt[(kt + br[i]) * 768 + bn + bc4[i]];
        }

        #pragma unroll
        for (int ks = 0; ks < 4; ks++) {
            uint32_t a[2][4];
            #pragma unroll
            for (int mi = 0; mi < 2; mi++)
                ldsm_x4(a[mi][0], a[mi][1], a[mi][2], a[mi][3],
                        a_base + (uint32_t)(mi * 16 * A_ROW_STRIDE + ks * 8) * 4u);
            uint32_t b[4][2];
            #pragma unroll
            for (int ni = 0; ni < 4; ni++) {
                int base = b_ld + ks * (8 * B_ROW_STRIDE) + ni * 8;
                b[ni][0] = Bc[base];
                b[ni][1] = Bc[base + 4 * B_ROW_STRIDE];
            }
            #pragma unroll
            for (int mi = 0; mi < 2; mi++)
                #pragma unroll
                for (int ni = 0; ni < 4; ni++)
                    mma_tf32(acc[mi][ni], a[mi], b[ni]);
        }

        if (kt8 < 7) {
            uint32_t* An = As + (cur ^ 1) * A_BUF;
            uint32_t* Bn = Bs + (cur ^ 1) * B_BUF;
            #pragma unroll
            for (int i = 0; i < 4; i++) *(uint4*)&An[a_st[i]] = pa[i];
            #pragma unroll
            for (int i = 0; i < 2; i++) *(uint4*)&Bn[b_st[i]] = pb[i];
            __syncthreads();
        }
    }

    int third = bn >> 8;
    float* outp = (third == 0) ? g_q : (third == 1) ? g_k : g_v;
    int lc_base = (bn & 255) + wn * 32;
    int gid = lane >> 2, tig = lane & 3;
    #pragma unroll
    for (int mi = 0; mi < 2; mi++) {
        int row0 = bm + wm * 32 + mi * 16 + gid;
        #pragma unroll
        for (int ni = 0; ni < 4; ni++) {
            int col = lc_base + ni * 8 + tig * 2;
            if (row0 < N_NODES)
                *(float2*)&outp[(size_t)row0 * G_DIM + col] =
                    make_float2(acc[mi][ni][0], acc[mi][ni][1]);
            if (row0 + 8 < N_NODES)
                *(float2*)&outp[(size_t)(row0 + 8) * G_DIM + col] =
                    make_float2(acc[mi][ni][2], acc[mi][ni][3]);
        }
    }
}

// ---------------- scan ----------------
__global__ __launch_bounds__(1024) void scan_phase1() {
    __shared__ int ws[32];
    int t = threadIdx.x;
    int lane = t & 31, wid = t >> 5;
    int idx = blockIdx.x * 1024 + t;
    int v = (idx < N_NODES) ? g_deg[idx] : 0;

    int x = v;
    #pragma unroll
    for (int o = 1; o < 32; o <<= 1) {
        int y = __shfl_up_sync(0xffffffffu, x, o);
        if (lane >= o) x += y;
    }
    if (lane == 31) ws[wid] = x;
    __syncthreads();
    if (wid == 0) {
        int w = ws[lane];
        #pragma unroll
        for (int o = 1; o < 32; o <<= 1) {
            int y = __shfl_up_sync(0xffffffffu, w, o);
            if (lane >= o) w += y;
        }
        ws[lane] = w;
    }
    __syncthreads();
    int ex = x - v + ((wid > 0) ? ws[wid - 1] : 0);
    if (idx < N_NODES) { g_off[idx] = ex; g_cur[idx] = 0; }
    if (t == 1023) g_bsum[blockIdx.x] = ex + v;
}

__global__ void scan_phase2() {
    int t = threadIdx.x;   // 32 threads
    int v = (t < 30) ? g_bsum[t] : 0;
    int x = v;
    #pragma unroll
    for (int o = 1; o < 32; o <<= 1) {
        int y = __shfl_up_sync(0xffffffffu, x, o);
        if (t >= o) x += y;
    }
    g_bsum[t] = x - v;
}

__global__ __launch_bounds__(1024) void scan_phase3() {
    int idx = blockIdx.x * 1024 + threadIdx.x;
    if (idx < N_NODES) g_off[idx] += g_bsum[blockIdx.x];
    if (idx == 0) g_off[N_NODES] = E_EDGES;
}

__global__ void scatter_kernel(const int* __restrict__ src, const int* __restrict__ dst) {
    int e = blockIdx.x * blockDim.x + threadIdx.x;
    if (e >= E_EDGES) return;
    int d = dst[e];
    int pos = atomicAdd(&g_cur[d], 1);
    g_csr_src[g_off[d] + pos] = src[e];
}

// ---------------- per-node attention: 64 threads (2 warps) per dst node ----------------
__device__ __forceinline__ float ex2f(float x) {
    float r;
    asm("ex2.approx.ftz.f32 %0, %1;" : "=f"(r) : "f"(x));
    return r;
}

__global__ __launch_bounds__(256) void attn_kernel(float* __restrict__ out) {
    int gtid = blockIdx.x * blockDim.x + threadIdx.x;
    int node = gtid >> 6;
    if (node >= N_NODES) return;
    int doff = gtid & 63;     // float4 index within the 256-dim row

    const float KS = ATT_SCALE * LOG2E;
    float4 kv = ((const float4*)(g_k + (size_t)node * G_DIM))[doff];
    kv.x *= KS; kv.y *= KS; kv.z *= KS; kv.w *= KS;

    float4 z = make_float4(0.f, 0.f, 0.f, 0.f);
    float4 a = make_float4(0.f, 0.f, 0.f, 0.f);

    int e   = g_off[node];
    int end = g_off[node + 1];

    for (; e + 4 <= end; e += 4) {
        int s0 = g_csr_src[e];
        int s1 = g_csr_src[e + 1];
        int s2 = g_csr_src[e + 2];
        int s3 = g_csr_src[e + 3];
        float4 q0 = ((const float4*)(g_q + (size_t)s0 * G_DIM))[doff];
        float4 v0 = ((const float4*)(g_v + (size_t)s0 * G_DIM))[doff];
        float4 q1 = ((const float4*)(g_q + (size_t)s1 * G_DIM))[doff];
        float4 v1 = ((const float4*)(g_v + (size_t)s1 * G_DIM))[doff];
        float4 q2 = ((const float4*)(g_q + (size_t)s2 * G_DIM))[doff];
        float4 v2 = ((const float4*)(g_v + (size_t)s2 * G_DIM))[doff];
        float4 q3 = ((const float4*)(g_q + (size_t)s3 * G_DIM))[doff];
        float4 v3 = ((const float4*)(g_v + (size_t)s3 * G_DIM))[doff];

        float p;
        p = ex2f(q0.x * kv.x); z.x += p; a.x = fmaf(p, v0.x, a.x);
        p = ex2f(q0.y * kv.y); z.y += p; a.y = fmaf(p, v0.y, a.y);
        p = ex2f(q0.z * kv.z); z.z += p; a.z = fmaf(p, v0.z, a.z);
        p = ex2f(q0.w * kv.w); z.w += p; a.w = fmaf(p, v0.w, a.w);
        p = ex2f(q1.x * kv.x); z.x += p; a.x = fmaf(p, v1.x, a.x);
        p = ex2f(q1.y * kv.y); z.y += p; a.y = fmaf(p, v1.y, a.y);
        p = ex2f(q1.z * kv.z); z.z += p; a.z = fmaf(p, v1.z, a.z);
        p = ex2f(q1.w * kv.w); z.w += p; a.w = fmaf(p, v1.w, a.w);
        p = ex2f(q2.x * kv.x); z.x += p; a.x = fmaf(p, v2.x, a.x);
        p = ex2f(q2.y * kv.y); z.y += p; a.y = fmaf(p, v2.y, a.y);
        p = ex2f(q2.z * kv.z); z.z += p; a.z = fmaf(p, v2.z, a.z);
        p = ex2f(q2.w * kv.w); z.w += p; a.w = fmaf(p, v2.w, a.w);
        p = ex2f(q3.x * kv.x); z.x += p; a.x = fmaf(p, v3.x, a.x);
        p = ex2f(q3.y * kv.y); z.y += p; a.y = fmaf(p, v3.y, a.y);
        p = ex2f(q3.z * kv.z); z.z += p; a.z = fmaf(p, v3.z, a.z);
        p = ex2f(q3.w * kv.w); z.w += p; a.w = fmaf(p, v3.w, a.w);
    }
    for (; e < end; e++) {
        int s0 = g_csr_src[e];
        float4 q0 = ((const float4*)(g_q + (size_t)s0 * G_DIM))[doff];
        float4 v0 = ((const float4*)(g_v + (size_t)s0 * G_DIM))[doff];
        float p;
        p = ex2f(q0.x * kv.x); z.x += p; a.x = fmaf(p, v0.x, a.x);
        p = ex2f(q0.y * kv.y); z.y += p; a.y = fmaf(p, v0.y, a.y);
        p = ex2f(q0.z * kv.z); z.z += p; a.z = fmaf(p, v0.z, a.z);
        p = ex2f(q0.w * kv.w); z.w += p; a.w = fmaf(p, v0.w, a.w);
    }

    float4 r;
    r.x = (z.x > 0.f) ? a.x / z.x : 0.f;
    r.y = (z.y > 0.f) ? a.y / z.y : 0.f;
    r.z = (z.z > 0.f) ? a.z / z.z : 0.f;
    r.w = (z.w > 0.f) ? a.w / z.w : 0.f;
    ((float4*)(out + (size_t)node * G_DIM))[doff] = r;
}

// ---------------- launch ----------------
// Order keeps the GEMM as the 4th launch (ncu -s capture window):
// zero_wconv(1), hist(2), ln(3), gemm(4), scan1(5), scan2(6), scan3(7), scatter(8), attn(9)
extern "C" void kernel_launch(void* const* d_in, const int* in_sizes, int n_in,
                              void* d_out, int out_size) {
    const float* s     = (const float*)d_in[0];
    const float* Wqkv  = (const float*)d_in[1];
    const float* gamma = (const float*)d_in[2];
    const float* beta  = (const float*)d_in[3];
    const int*   src   = (const int*)d_in[4];
    const int*   dst   = (const int*)d_in[5];
    float* out = (float*)d_out;

    static int smem_cfg_done = 0;
    if (!smem_cfg_done) {
        cudaFuncSetAttribute(qkv_gemm_tf32_kernel,
                             cudaFuncAttributeMaxDynamicSharedMemorySize,
                             GEMM_SMEM_BYTES);
        smem_cfg_done = 1;
    }

    zero_wconv_kernel<<<(W_VEC4 + 255) / 256, 256>>>(Wqkv);
    hist_kernel<<<(E_EDGES + 255) / 256, 256>>>(dst);
    ln_kernel<<<(N_NODES * 32 + 255) / 256, 256>>>(s, gamma, beta);

    dim3 gemm_grid(768 / 64, (N_NODES + 127) / 128);
    qkv_gemm_tf32_kernel<<<gemm_grid, 256, GEMM_SMEM_BYTES>>>();

    const int SCAN_BLOCKS = (N_NODES + 1023) / 1024;   // 30
    scan_phase1<<<SCAN_BLOCKS, 1024>>>();
    scan_phase2<<<1, 32>>>();
    scan_phase3<<<SCAN_BLOCKS, 1024>>>();

    scatter_kernel<<<(E_EDGES + 255) / 256, 256>>>(src, dst);

    attn_kernel<<<(N_NODES * 64 + 255) / 256, 256>>>(out);
}

// round 15
// speedup vs baseline: 1.9088x; 1.6392x over previous
#include <cuda_runtime.h>
#include <math.h>
#include <stdint.h>

#define N_NODES 30000
#define E_EDGES 480000
#define G_DIM   256
#define ATT_SCALE 0.0625f   /* 256^-0.5 */
#define LOG2E   1.4426950408889634f
#define LN_EPS  1e-5f

// natural-layout smem tiles (word strides chosen for conflict-free access)
#define A_ROW_STRIDE 36                    /* 32 cols + 4 pad  (≡4 mod 32) */
#define A_BUF (128 * A_ROW_STRIDE)         /* 4608 words */
#define B_ROW_STRIDE 136                   /* 128 cols + 8 pad (≡8 mod 32) */
#define B_BUF (32 * B_ROW_STRIDE)          /* 4352 words */
#define GEMM_SMEM_BYTES ((2 * A_BUF + 2 * B_BUF) * 4)   /* 71680 */

#define W_ELEMS (G_DIM * 768)              /* 196608 */
#define W_VEC4  (W_ELEMS / 4)              /* 49152 */

// ---------------- device scratch (static allocation only) ----------------
__device__ float    g_x[N_NODES * G_DIM];   // LN output, pre-rounded to tf32
__device__ uint32_t g_wt[W_ELEMS];          // W pre-rounded to tf32 bits
__device__ float    g_q[N_NODES * G_DIM];
__device__ float    g_k[N_NODES * G_DIM];
__device__ float    g_v[N_NODES * G_DIM];
__device__ int      g_deg[N_NODES];
__device__ int      g_cur[N_NODES];
__device__ int      g_off[N_NODES + 1];
__device__ int      g_csr_src[E_EDGES];
__device__ int      g_bsum[32];

// ---------------- tf32 / async helpers ----------------
__device__ __forceinline__ uint32_t to_tf32(float x) {
    uint32_t t;
    asm("cvt.rna.tf32.f32 %0, %1;" : "=r"(t) : "f"(x));
    return t;
}

__device__ __forceinline__ void mma_tf32(float c[4], const uint32_t a[4], const uint32_t b[2]) {
    asm volatile(
        "mma.sync.aligned.m16n8k8.row.col.f32.tf32.tf32.f32 "
        "{%0,%1,%2,%3}, {%4,%5,%6,%7}, {%8,%9}, {%0,%1,%2,%3};"
        : "+f"(c[0]), "+f"(c[1]), "+f"(c[2]), "+f"(c[3])
        : "r"(a[0]), "r"(a[1]), "r"(a[2]), "r"(a[3]), "r"(b[0]), "r"(b[1]));
}

__device__ __forceinline__ void ldsm_x4(uint32_t& r0, uint32_t& r1, uint32_t& r2,
                                        uint32_t& r3, uint32_t saddr) {
    asm volatile("ldmatrix.sync.aligned.m8n8.x4.shared.b16 {%0,%1,%2,%3}, [%4];"
                 : "=r"(r0), "=r"(r1), "=r"(r2), "=r"(r3) : "r"(saddr));
}

__device__ __forceinline__ void cp_async16(uint32_t dst_sh, const void* src, int src_sz) {
    asm volatile("cp.async.cg.shared.global [%0], [%1], 16, %2;"
                 :: "r"(dst_sh), "l"(src), "r"(src_sz));
}
__device__ __forceinline__ void cp_commit() {
    asm volatile("cp.async.commit_group;");
}
template <int N>
__device__ __forceinline__ void cp_wait() {
    asm volatile("cp.async.wait_group %0;" :: "n"(N));
}

// ---------------- zero g_deg + pre-convert W to tf32 ----------------
__global__ void zero_wconv_kernel(const float* __restrict__ W) {
    int i = blockIdx.x * blockDim.x + threadIdx.x;
    if (i < N_NODES) g_deg[i] = 0;
    if (i < W_VEC4) {
        float4 f = ((const float4*)W)[i];
        ((uint4*)g_wt)[i] = make_uint4(to_tf32(f.x), to_tf32(f.y),
                                       to_tf32(f.z), to_tf32(f.w));
    }
}

// ---------------- CSR histogram ----------------
__global__ void hist_kernel(const int* __restrict__ dst) {
    int e = blockIdx.x * blockDim.x + threadIdx.x;
    if (e < E_EDGES) atomicAdd(&g_deg[dst[e]], 1);
}

// ---------------- LayerNorm (stats + apply + tf32 round), one warp per row ----------------
__global__ void ln_kernel(const float* __restrict__ s,
                          const float* __restrict__ gamma,
                          const float* __restrict__ beta) {
    int gtid = blockIdx.x * blockDim.x + threadIdx.x;
    int row = gtid >> 5;
    if (row >= N_NODES) return;
    int lane = threadIdx.x & 31;

    const float4* p = (const float4*)(s + (size_t)row * G_DIM);
    float4 f0 = p[lane];
    float4 f1 = p[lane + 32];
    float sum = f0.x + f0.y + f0.z + f0.w + f1.x + f1.y + f1.z + f1.w;
    float sq  = f0.x*f0.x + f0.y*f0.y + f0.z*f0.z + f0.w*f0.w
              + f1.x*f1.x + f1.y*f1.y + f1.z*f1.z + f1.w*f1.w;
    #pragma unroll
    for (int o = 16; o > 0; o >>= 1) {
        sum += __shfl_xor_sync(0xffffffffu, sum, o);
        sq  += __shfl_xor_sync(0xffffffffu, sq, o);
    }
    float mu = sum * (1.f / G_DIM);
    float rs = rsqrtf(sq * (1.f / G_DIM) - mu * mu + LN_EPS);

    float4 ga = ((const float4*)gamma)[lane];
    float4 gb = ((const float4*)gamma)[lane + 32];
    float4 ba = ((const float4*)beta)[lane];
    float4 bb = ((const float4*)beta)[lane + 32];
    float4 o0, o1;
    o0.x = __uint_as_float(to_tf32((f0.x - mu) * rs * ga.x + ba.x));
    o0.y = __uint_as_float(to_tf32((f0.y - mu) * rs * ga.y + ba.y));
    o0.z = __uint_as_float(to_tf32((f0.z - mu) * rs * ga.z + ba.z));
    o0.w = __uint_as_float(to_tf32((f0.w - mu) * rs * ga.w + ba.w));
    o1.x = __uint_as_float(to_tf32((f1.x - mu) * rs * gb.x + bb.x));
    o1.y = __uint_as_float(to_tf32((f1.y - mu) * rs * gb.y + bb.y));
    o1.z = __uint_as_float(to_tf32((f1.z - mu) * rs * gb.z + bb.z));
    o1.w = __uint_as_float(to_tf32((f1.w - mu) * rs * gb.w + bb.w));
    float4* op = (float4*)(g_x + (size_t)row * G_DIM);
    op[lane]      = o0;
    op[lane + 32] = o1;
}

// ---------------- QKV GEMM (tf32, 128x128 block tile, cp.async staging) ----------------
// C[N,768] = X[N,256] @ W[256,768]; K-chunk 32; 8 warps (4M x 2N), warp tile 32x64.
__global__ __launch_bounds__(256, 2) void qkv_gemm_tf32_kernel() {

    extern __shared__ uint32_t smem[];

    int tid  = threadIdx.x;
    int warp = tid >> 5;
    int lane = tid & 31;
    int wm = warp >> 1;          // 0..3 (M)
    int wn = warp & 1;           // 0..1 (N)
    int bm = blockIdx.y * 128;
    int bn = blockIdx.x * 128;

    float acc[2][8][4];
    #pragma unroll
    for (int mi = 0; mi < 2; mi++)
        #pragma unroll
        for (int ni = 0; ni < 8; ni++)
            #pragma unroll
            for (int r = 0; r < 4; r++) acc[mi][ni][r] = 0.f;

    // staging coordinates (loop-invariant)
    int ar[4], ac4[4], a_st[4], asz[4];
    #pragma unroll
    for (int i = 0; i < 4; i++) {
        int idx = tid + i * 256;
        ar[i]  = idx >> 3;            // 0..127
        ac4[i] = (idx & 7) * 4;       // 0..28
        a_st[i] = ar[i] * A_ROW_STRIDE + ac4[i];
        asz[i] = (bm + ar[i] < N_NODES) ? 16 : 0;
    }
    int br[4], bc4[4], b_st[4];
    #pragma unroll
    for (int i = 0; i < 4; i++) {
        int idx = tid + i * 256;
        br[i]  = idx >> 5;            // 0..31
        bc4[i] = (idx & 31) * 4;      // 0..124
        b_st[i] = br[i] * B_ROW_STRIDE + bc4[i];
    }
    // clamped A row pointers (cp.async src must be valid even when sz=0)
    const float* a_src[4];
    #pragma unroll
    for (int i = 0; i < 4; i++) {
        int gr = bm + ar[i];
        if (gr >= N_NODES) gr = N_NODES - 1;
        a_src[i] = g_x + (size_t)gr * G_DIM + ac4[i];
    }

    uint32_t smem_sh = (uint32_t)__cvta_generic_to_shared(smem);

    // ldmatrix per-lane addresses for A (x4 tiles: (r,c) (r+8,c) (r,c+4) (r+8,c+4))
    int lr = lane & 7, tile = lane >> 3;
    int a_row = wm * 32 + (tile & 1) * 8 + lr;
    int a_colw = (tile >> 1) * 4;
    uint32_t a_sm0 = smem_sh + (uint32_t)(a_row * A_ROW_STRIDE + a_colw) * 4u;

    // B fragment LDS offsets (conflict-free: 8*(l&3) + (l>>2) bijection mod 32)
    int b_ld = (lane & 3) * B_ROW_STRIDE + wn * 64 + (lane >> 2);

    // ---- prologue: async-stage K-tile 0 into buffer 0
    {
        uint32_t aB = smem_sh;
        uint32_t bB = smem_sh + (uint32_t)(2 * A_BUF) * 4u;
        #pragma unroll
        for (int i = 0; i < 4; i++)
            cp_async16(aB + (uint32_t)a_st[i] * 4u, a_src[i], asz[i]);
        #pragma unroll
        for (int i = 0; i < 4; i++)
            cp_async16(bB + (uint32_t)b_st[i] * 4u, g_wt + br[i] * 768 + bn + bc4[i], 16);
        cp_commit();
    }

    for (int kt8 = 0; kt8 < 8; kt8++) {
        int cur = kt8 & 1;

        // issue next tile into the other buffer (safe: freed by end-of-prev-iter sync)
        if (kt8 < 7) {
            int kt = (kt8 + 1) * 32;
            int nxt = cur ^ 1;
            uint32_t aB = smem_sh + (uint32_t)(nxt * A_BUF) * 4u;
            uint32_t bB = smem_sh + (uint32_t)(2 * A_BUF + nxt * B_BUF) * 4u;
            #pragma unroll
            for (int i = 0; i < 4; i++)
                cp_async16(aB + (uint32_t)a_st[i] * 4u, a_src[i] + kt, asz[i]);
            #pragma unroll
            for (int i = 0; i < 4; i++)
                cp_async16(bB + (uint32_t)b_st[i] * 4u,
                           g_wt + (kt + br[i]) * 768 + bn + bc4[i], 16);
            cp_commit();
            cp_wait<1>();       // current tile's group done
        } else {
            cp_wait<0>();
        }
        __syncthreads();        // staged data visible to all warps

        const uint32_t* Bc = smem + 2 * A_BUF + cur * B_BUF;
        uint32_t a_base = a_sm0 + (uint32_t)(cur * A_BUF) * 4u;

        #pragma unroll
        for (int ks = 0; ks < 4; ks++) {
            uint32_t a[2][4];
            #pragma unroll
            for (int mi = 0; mi < 2; mi++)
                ldsm_x4(a[mi][0], a[mi][1], a[mi][2], a[mi][3],
                        a_base + (uint32_t)(mi * 16 * A_ROW_STRIDE + ks * 8) * 4u);
            uint32_t b[8][2];
            #pragma unroll
            for (int ni = 0; ni < 8; ni++) {
                int base = b_ld + ks * (8 * B_ROW_STRIDE) + ni * 8;
                b[ni][0] = Bc[base];
                b[ni][1] = Bc[base + 4 * B_ROW_STRIDE];
            }
            #pragma unroll
            for (int mi = 0; mi < 2; mi++)
                #pragma unroll
                for (int ni = 0; ni < 8; ni++)
                    mma_tf32(acc[mi][ni], a[mi], b[ni]);
        }

        if (kt8 < 7) __syncthreads();   // protect cur buffer before it is re-staged
    }

    // ---- epilogue: route to q/k/v (128-col tile lies fully inside one third)
    int third = bn >> 8;
    float* outp = (third == 0) ? g_q : (third == 1) ? g_k : g_v;
    int lc_base = (bn & 255) + wn * 64;
    int gid = lane >> 2, tig = lane & 3;
    #pragma unroll
    for (int mi = 0; mi < 2; mi++) {
        int row0 = bm + wm * 32 + mi * 16 + gid;
        #pragma unroll
        for (int ni = 0; ni < 8; ni++) {
            int col = lc_base + ni * 8 + tig * 2;
            if (row0 < N_NODES)
                *(float2*)&outp[(size_t)row0 * G_DIM + col] =
                    make_float2(acc[mi][ni][0], acc[mi][ni][1]);
            if (row0 + 8 < N_NODES)
                *(float2*)&outp[(size_t)(row0 + 8) * G_DIM + col] =
                    make_float2(acc[mi][ni][2], acc[mi][ni][3]);
        }
    }
}

// ---------------- scan ----------------
__global__ __launch_bounds__(1024) void scan_phase1() {
    __shared__ int ws[32];
    int t = threadIdx.x;
    int lane = t & 31, wid = t >> 5;
    int idx = blockIdx.x * 1024 + t;
    int v = (idx < N_NODES) ? g_deg[idx] : 0;

    int x = v;
    #pragma unroll
    for (int o = 1; o < 32; o <<= 1) {
        int y = __shfl_up_sync(0xffffffffu, x, o);
        if (lane >= o) x += y;
    }
    if (lane == 31) ws[wid] = x;
    __syncthreads();
    if (wid == 0) {
        int w = ws[lane];
        #pragma unroll
        for (int o = 1; o < 32; o <<= 1) {
            int y = __shfl_up_sync(0xffffffffu, w, o);
            if (lane >= o) w += y;
        }
        ws[lane] = w;
    }
    __syncthreads();
    int ex = x - v + ((wid > 0) ? ws[wid - 1] : 0);
    if (idx < N_NODES) { g_off[idx] = ex; g_cur[idx] = 0; }
    if (t == 1023) g_bsum[blockIdx.x] = ex + v;
}

__global__ void scan_phase2() {
    int t = threadIdx.x;   // 32 threads
    int v = (t < 30) ? g_bsum[t] : 0;
    int x = v;
    #pragma unroll
    for (int o = 1; o < 32; o <<= 1) {
        int y = __shfl_up_sync(0xffffffffu, x, o);
        if (t >= o) x += y;
    }
    g_bsum[t] = x - v;
}

__global__ __launch_bounds__(1024) void scan_phase3() {
    int idx = blockIdx.x * 1024 + threadIdx.x;
    if (idx < N_NODES) g_off[idx] += g_bsum[blockIdx.x];
    if (idx == 0) g_off[N_NODES] = E_EDGES;
}

__global__ void scatter_kernel(const int* __restrict__ src, const int* __restrict__ dst) {
    int e = blockIdx.x * blockDim.x + threadIdx.x;
    if (e >= E_EDGES) return;
    int d = dst[e];
    int pos = atomicAdd(&g_cur[d], 1);
    g_csr_src[g_off[d] + pos] = src[e];
}

// ---------------- per-node attention: 64 threads (2 warps) per dst node ----------------
__device__ __forceinline__ float ex2f(float x) {
    float r;
    asm("ex2.approx.ftz.f32 %0, %1;" : "=f"(r) : "f"(x));
    return r;
}

__global__ __launch_bounds__(256) void attn_kernel(float* __restrict__ out) {
    int gtid = blockIdx.x * blockDim.x + threadIdx.x;
    int node = gtid >> 6;
    if (node >= N_NODES) return;
    int doff = gtid & 63;     // float4 index within the 256-dim row

    const float KS = ATT_SCALE * LOG2E;
    float4 kv = ((const float4*)(g_k + (size_t)node * G_DIM))[doff];
    kv.x *= KS; kv.y *= KS; kv.z *= KS; kv.w *= KS;

    float4 z = make_float4(0.f, 0.f, 0.f, 0.f);
    float4 a = make_float4(0.f, 0.f, 0.f, 0.f);

    int e   = g_off[node];
    int end = g_off[node + 1];

    for (; e + 4 <= end; e += 4) {
        int s0 = g_csr_src[e];
        int s1 = g_csr_src[e + 1];
        int s2 = g_csr_src[e + 2];
        int s3 = g_csr_src[e + 3];
        float4 q0 = ((const float4*)(g_q + (size_t)s0 * G_DIM))[doff];
        float4 v0 = ((const float4*)(g_v + (size_t)s0 * G_DIM))[doff];
        float4 q1 = ((const float4*)(g_q + (size_t)s1 * G_DIM))[doff];
        float4 v1 = ((const float4*)(g_v + (size_t)s1 * G_DIM))[doff];
        float4 q2 = ((const float4*)(g_q + (size_t)s2 * G_DIM))[doff];
        float4 v2 = ((const float4*)(g_v + (size_t)s2 * G_DIM))[doff];
        float4 q3 = ((const float4*)(g_q + (size_t)s3 * G_DIM))[doff];
        float4 v3 = ((const float4*)(g_v + (size_t)s3 * G_DIM))[doff];

        float p;
        p = ex2f(q0.x * kv.x); z.x += p; a.x = fmaf(p, v0.x, a.x);
        p = ex2f(q0.y * kv.y); z.y += p; a.y = fmaf(p, v0.y, a.y);
        p = ex2f(q0.z * kv.z); z.z += p; a.z = fmaf(p, v0.z, a.z);
        p = ex2f(q0.w * kv.w); z.w += p; a.w = fmaf(p, v0.w, a.w);
        p = ex2f(q1.x * kv.x); z.x += p; a.x = fmaf(p, v1.x, a.x);
        p = ex2f(q1.y * kv.y); z.y += p; a.y = fmaf(p, v1.y, a.y);
        p = ex2f(q1.z * kv.z); z.z += p; a.z = fmaf(p, v1.z, a.z);
        p = ex2f(q1.w * kv.w); z.w += p; a.w = fmaf(p, v1.w, a.w);
        p = ex2f(q2.x * kv.x); z.x += p; a.x = fmaf(p, v2.x, a.x);
        p = ex2f(q2.y * kv.y); z.y += p; a.y = fmaf(p, v2.y, a.y);
        p = ex2f(q2.z * kv.z); z.z += p; a.z = fmaf(p, v2.z, a.z);
        p = ex2f(q2.w * kv.w); z.w += p; a.w = fmaf(p, v2.w, a.w);
        p = ex2f(q3.x * kv.x); z.x += p; a.x = fmaf(p, v3.x, a.x);
        p = ex2f(q3.y * kv.y); z.y += p; a.y = fmaf(p, v3.y, a.y);
        p = ex2f(q3.z * kv.z); z.z += p; a.z = fmaf(p, v3.z, a.z);
        p = ex2f(q3.w * kv.w); z.w += p; a.w = fmaf(p, v3.w, a.w);
    }
    for (; e < end; e++) {
        int s0 = g_csr_src[e];
        float4 q0 = ((const float4*)(g_q + (size_t)s0 * G_DIM))[doff];
        float4 v0 = ((const float4*)(g_v + (size_t)s0 * G_DIM))[doff];
        float p;
        p = ex2f(q0.x * kv.x); z.x += p; a.x = fmaf(p, v0.x, a.x);
        p = ex2f(q0.y * kv.y); z.y += p; a.y = fmaf(p, v0.y, a.y);
        p = ex2f(q0.z * kv.z); z.z += p; a.z = fmaf(p, v0.z, a.z);
        p = ex2f(q0.w * kv.w); z.w += p; a.w = fmaf(p, v0.w, a.w);
    }

    float4 r;
    r.x = (z.x > 0.f) ? a.x / z.x : 0.f;
    r.y = (z.y > 0.f) ? a.y / z.y : 0.f;
    r.z = (z.z > 0.f) ? a.z / z.z : 0.f;
    r.w = (z.w > 0.f) ? a.w / z.w : 0.f;
    ((float4*)(out + (size_t)node * G_DIM))[doff] = r;
}

// ---------------- launch ----------------
// Order keeps the GEMM as the 4th launch (ncu -s capture window):
// zero_wconv(1), hist(2), ln(3), gemm(4), scan1(5), scan2(6), scan3(7), scatter(8), attn(9)
extern "C" void kernel_launch(void* const* d_in, const int* in_sizes, int n_in,
                              void* d_out, int out_size) {
    const float* s     = (const float*)d_in[0];
    const float* Wqkv  = (const float*)d_in[1];
    const float* gamma = (const float*)d_in[2];
    const float* beta  = (const float*)d_in[3];
    const int*   src   = (const int*)d_in[4];
    const int*   dst   = (const int*)d_in[5];
    float* out = (float*)d_out;

    static int smem_cfg_done = 0;
    if (!smem_cfg_done) {
        cudaFuncSetAttribute(qkv_gemm_tf32_kernel,
                             cudaFuncAttributeMaxDynamicSharedMemorySize,
                             GEMM_SMEM_BYTES);
        smem_cfg_done = 1;
    }

    zero_wconv_kernel<<<(W_VEC4 + 255) / 256, 256>>>(Wqkv);
    hist_kernel<<<(E_EDGES + 255) / 256, 256>>>(dst);
    ln_kernel<<<(N_NODES * 32 + 255) / 256, 256>>>(s, gamma, beta);

    dim3 gemm_grid(768 / 128, (N_NODES + 127) / 128);   // 6 x 235
    qkv_gemm_tf32_kernel<<<gemm_grid, 256, GEMM_SMEM_BYTES>>>();

    const int SCAN_BLOCKS = (N_NODES + 1023) / 1024;   // 30
    scan_phase1<<<SCAN_BLOCKS, 1024>>>();
    scan_phase2<<<1, 32>>>();
    scan_phase3<<<SCAN_BLOCKS, 1024>>>();

    scatter_kernel<<<(E_EDGES + 255) / 256, 256>>>(src, dst);

    attn_kernel<<<(N_NODES * 64 + 255) / 256, 256>>>(out);
}

// round 16
// speedup vs baseline: 1.9305x; 1.0114x over previous
#include <cuda_runtime.h>
#include <math.h>
#include <stdint.h>

#define N_NODES 30000
#define E_EDGES 480000
#define G_DIM   256
#define ATT_SCALE 0.0625f   /* 256^-0.5 */
#define LOG2E   1.4426950408889634f
#define LN_EPS  1e-5f

// natural-layout smem tiles (word strides chosen for conflict-free access)
#define A_ROW_STRIDE 36                    /* 32 cols + 4 pad  (≡4 mod 32) */
#define A_BUF (128 * A_ROW_STRIDE)         /* 4608 words */
#define B_ROW_STRIDE 136                   /* 128 cols + 8 pad (≡8 mod 32) */
#define B_BUF (32 * B_ROW_STRIDE)          /* 4352 words */
#define STAGE_WORDS (A_BUF + B_BUF)        /* 8960 */
#define N_STAGES 3
#define GEMM_SMEM_BYTES (N_STAGES * STAGE_WORDS * 4)    /* 107520 */

#define W_ELEMS (G_DIM * 768)              /* 196608 */
#define W_VEC4  (W_ELEMS / 4)              /* 49152 */

// ---------------- device scratch (static allocation only) ----------------
__device__ float    g_x[N_NODES * G_DIM];   // LN output, pre-rounded to tf32
__device__ uint32_t g_wt[W_ELEMS];          // W pre-rounded to tf32 bits
__device__ float    g_q[N_NODES * G_DIM];
__device__ float    g_k[N_NODES * G_DIM];
__device__ float    g_v[N_NODES * G_DIM];
__device__ int      g_deg[N_NODES];
__device__ int      g_cur[N_NODES];
__device__ int      g_off[N_NODES + 1];
__device__ int      g_csr_src[E_EDGES];
__device__ int      g_bsum[32];

// ---------------- tf32 / async helpers ----------------
__device__ __forceinline__ uint32_t to_tf32(float x) {
    uint32_t t;
    asm("cvt.rna.tf32.f32 %0, %1;" : "=r"(t) : "f"(x));
    return t;
}

__device__ __forceinline__ void mma_tf32(float c[4], const uint32_t a[4], const uint32_t b[2]) {
    asm volatile(
        "mma.sync.aligned.m16n8k8.row.col.f32.tf32.tf32.f32 "
        "{%0,%1,%2,%3}, {%4,%5,%6,%7}, {%8,%9}, {%0,%1,%2,%3};"
        : "+f"(c[0]), "+f"(c[1]), "+f"(c[2]), "+f"(c[3])
        : "r"(a[0]), "r"(a[1]), "r"(a[2]), "r"(a[3]), "r"(b[0]), "r"(b[1]));
}

__device__ __forceinline__ void ldsm_x4(uint32_t& r0, uint32_t& r1, uint32_t& r2,
                                        uint32_t& r3, uint32_t saddr) {
    asm volatile("ldmatrix.sync.aligned.m8n8.x4.shared.b16 {%0,%1,%2,%3}, [%4];"
                 : "=r"(r0), "=r"(r1), "=r"(r2), "=r"(r3) : "r"(saddr));
}

__device__ __forceinline__ void cp_async16(uint32_t dst_sh, const void* src, int src_sz) {
    asm volatile("cp.async.cg.shared.global [%0], [%1], 16, %2;"
                 :: "r"(dst_sh), "l"(src), "r"(src_sz));
}
__device__ __forceinline__ void cp_commit() {
    asm volatile("cp.async.commit_group;");
}
template <int N>
__device__ __forceinline__ void cp_wait() {
    asm volatile("cp.async.wait_group %0;" :: "n"(N));
}

// ---------------- zero g_deg + pre-convert W to tf32 ----------------
__global__ void zero_wconv_kernel(const float* __restrict__ W) {
    int i = blockIdx.x * blockDim.x + threadIdx.x;
    if (i < N_NODES) g_deg[i] = 0;
    if (i < W_VEC4) {
        float4 f = ((const float4*)W)[i];
        ((uint4*)g_wt)[i] = make_uint4(to_tf32(f.x), to_tf32(f.y),
                                       to_tf32(f.z), to_tf32(f.w));
    }
}

// ---------------- CSR histogram ----------------
__global__ void hist_kernel(const int* __restrict__ dst) {
    int e = blockIdx.x * blockDim.x + threadIdx.x;
    if (e < E_EDGES) atomicAdd(&g_deg[dst[e]], 1);
}

// ---------------- LayerNorm (stats + apply + tf32 round), one warp per row ----------------
__global__ void ln_kernel(const float* __restrict__ s,
                          const float* __restrict__ gamma,
                          const float* __restrict__ beta) {
    int gtid = blockIdx.x * blockDim.x + threadIdx.x;
    int row = gtid >> 5;
    if (row >= N_NODES) return;
    int lane = threadIdx.x & 31;

    const float4* p = (const float4*)(s + (size_t)row * G_DIM);
    float4 f0 = p[lane];
    float4 f1 = p[lane + 32];
    float sum = f0.x + f0.y + f0.z + f0.w + f1.x + f1.y + f1.z + f1.w;
    float sq  = f0.x*f0.x + f0.y*f0.y + f0.z*f0.z + f0.w*f0.w
              + f1.x*f1.x + f1.y*f1.y + f1.z*f1.z + f1.w*f1.w;
    #pragma unroll
    for (int o = 16; o > 0; o >>= 1) {
        sum += __shfl_xor_sync(0xffffffffu, sum, o);
        sq  += __shfl_xor_sync(0xffffffffu, sq, o);
    }
    float mu = sum * (1.f / G_DIM);
    float rs = rsqrtf(sq * (1.f / G_DIM) - mu * mu + LN_EPS);

    float4 ga = ((const float4*)gamma)[lane];
    float4 gb = ((const float4*)gamma)[lane + 32];
    float4 ba = ((const float4*)beta)[lane];
    float4 bb = ((const float4*)beta)[lane + 32];
    float4 o0, o1;
    o0.x = __uint_as_float(to_tf32((f0.x - mu) * rs * ga.x + ba.x));
    o0.y = __uint_as_float(to_tf32((f0.y - mu) * rs * ga.y + ba.y));
    o0.z = __uint_as_float(to_tf32((f0.z - mu) * rs * ga.z + ba.z));
    o0.w = __uint_as_float(to_tf32((f0.w - mu) * rs * ga.w + ba.w));
    o1.x = __uint_as_float(to_tf32((f1.x - mu) * rs * gb.x + bb.x));
    o1.y = __uint_as_float(to_tf32((f1.y - mu) * rs * gb.y + bb.y));
    o1.z = __uint_as_float(to_tf32((f1.z - mu) * rs * gb.z + bb.z));
    o1.w = __uint_as_float(to_tf32((f1.w - mu) * rs * gb.w + bb.w));
    float4* op = (float4*)(g_x + (size_t)row * G_DIM);
    op[lane]      = o0;
    op[lane + 32] = o1;
}

// ---------------- QKV GEMM (tf32, 128x128 tile, 3-stage cp.async ring) ----------------
// C[N,768] = X[N,256] @ W[256,768]; K-chunk 32; 8 warps (4M x 2N), warp tile 32x64.
// Per K-tile: wait -> sync -> compute -> issue(i+2). One sync per iteration;
// the waited tile was issued two compute-phases earlier, so the wait is ~free.
__global__ __launch_bounds__(256, 2) void qkv_gemm_tf32_kernel() {

    extern __shared__ uint32_t smem[];

    int tid  = threadIdx.x;
    int warp = tid >> 5;
    int lane = tid & 31;
    int wm = warp >> 1;          // 0..3 (M)
    int wn = warp & 1;           // 0..1 (N)
    int bm = blockIdx.y * 128;
    int bn = blockIdx.x * 128;

    float acc[2][8][4];
    #pragma unroll
    for (int mi = 0; mi < 2; mi++)
        #pragma unroll
        for (int ni = 0; ni < 8; ni++)
            #pragma unroll
            for (int r = 0; r < 4; r++) acc[mi][ni][r] = 0.f;

    // staging coordinates (loop-invariant)
    int ar[4], ac4[4], a_st[4], asz[4];
    #pragma unroll
    for (int i = 0; i < 4; i++) {
        int idx = tid + i * 256;
        ar[i]  = idx >> 3;            // 0..127
        ac4[i] = (idx & 7) * 4;       // 0..28
        a_st[i] = ar[i] * A_ROW_STRIDE + ac4[i];
        asz[i] = (bm + ar[i] < N_NODES) ? 16 : 0;
    }
    int br[4], bc4[4], b_st[4];
    #pragma unroll
    for (int i = 0; i < 4; i++) {
        int idx = tid + i * 256;
        br[i]  = idx >> 5;            // 0..31
        bc4[i] = (idx & 31) * 4;      // 0..124
        b_st[i] = A_BUF + br[i] * B_ROW_STRIDE + bc4[i];  // B sits after A in a stage
    }
    // clamped A row pointers (cp.async src must be valid even when sz=0)
    const float* a_src[4];
    #pragma unroll
    for (int i = 0; i < 4; i++) {
        int gr = bm + ar[i];
        if (gr >= N_NODES) gr = N_NODES - 1;
        a_src[i] = g_x + (size_t)gr * G_DIM + ac4[i];
    }

    uint32_t smem_sh = (uint32_t)__cvta_generic_to_shared(smem);

    // ldmatrix per-lane addresses for A (x4 tiles: (r,c) (r+8,c) (r,c+4) (r+8,c+4))
    int lr = lane & 7, tile = lane >> 3;
    int a_row = wm * 32 + (tile & 1) * 8 + lr;
    int a_colw = (tile >> 1) * 4;
    uint32_t a_sm0 = smem_sh + (uint32_t)(a_row * A_ROW_STRIDE + a_colw) * 4u;

    // B fragment LDS offsets (conflict-free: 8*(l&3) + (l>>2) bijection mod 32)
    int b_ld = A_BUF + (lane & 3) * B_ROW_STRIDE + wn * 64 + (lane >> 2);

    // ---- prologue: async-stage K-tiles 0 and 1 into stages 0, 1
    #pragma unroll
    for (int st = 0; st < 2; st++) {
        uint32_t base = smem_sh + (uint32_t)(st * STAGE_WORDS) * 4u;
        int kt = st * 32;
        #pragma unroll
        for (int i = 0; i < 4; i++)
            cp_async16(base + (uint32_t)a_st[i] * 4u, a_src[i] + kt, asz[i]);
        #pragma unroll
        for (int i = 0; i < 4; i++)
            cp_async16(base + (uint32_t)b_st[i] * 4u,
                       g_wt + (kt + br[i]) * 768 + bn + bc4[i], 16);
        cp_commit();
    }

    int cur = 0;                 // stage index of tile kt8
    for (int kt8 = 0; kt8 < 8; kt8++) {
        // wait for tile kt8 (1 group may remain in flight; tail: 0)
        if (kt8 < 7) cp_wait<1>(); else cp_wait<0>();
        __syncthreads();

        const uint32_t* Bc = smem + cur * STAGE_WORDS;
        uint32_t a_base = a_sm0 + (uint32_t)(cur * STAGE_WORDS) * 4u;

        #pragma unroll
        for (int ks = 0; ks < 4; ks++) {
            uint32_t a[2][4];
            #pragma unroll
            for (int mi = 0; mi < 2; mi++)
                ldsm_x4(a[mi][0], a[mi][1], a[mi][2], a[mi][3],
                        a_base + (uint32_t)(mi * 16 * A_ROW_STRIDE + ks * 8) * 4u);
            uint32_t b[8][2];
            #pragma unroll
            for (int ni = 0; ni < 8; ni++) {
                int base = b_ld + ks * (8 * B_ROW_STRIDE) + ni * 8;
                b[ni][0] = Bc[base];
                b[ni][1] = Bc[base + 4 * B_ROW_STRIDE];
            }
            #pragma unroll
            for (int mi = 0; mi < 2; mi++)
                #pragma unroll
                for (int ni = 0; ni < 8; ni++)
                    mma_tf32(acc[mi][ni], a[mi], b[ni]);
        }

        // issue tile kt8+2 into the stage freed at iteration kt8-1
        if (kt8 < 6) {
            int kt = (kt8 + 2) * 32;
            int nst = cur + 2; if (nst >= N_STAGES) nst -= N_STAGES;
            uint32_t base = smem_sh + (uint32_t)(nst * STAGE_WORDS) * 4u;
            #pragma unroll
            for (int i = 0; i < 4; i++)
                cp_async16(base + (uint32_t)a_st[i] * 4u, a_src[i] + kt, asz[i]);
            #pragma unroll
            for (int i = 0; i < 4; i++)
                cp_async16(base + (uint32_t)b_st[i] * 4u,
                           g_wt + (kt + br[i]) * 768 + bn + bc4[i], 16);
            cp_commit();
        }
        if (++cur == N_STAGES) cur = 0;
    }

    // ---- epilogue: route to q/k/v (128-col tile lies fully inside one third)
    int third = bn >> 8;
    float* outp = (third == 0) ? g_q : (third == 1) ? g_k : g_v;
    int lc_base = (bn & 255) + wn * 64;
    int gid = lane >> 2, tig = lane & 3;
    #pragma unroll
    for (int mi = 0; mi < 2; mi++) {
        int row0 = bm + wm * 32 + mi * 16 + gid;
        #pragma unroll
        for (int ni = 0; ni < 8; ni++) {
            int col = lc_base + ni * 8 + tig * 2;
            if (row0 < N_NODES)
                *(float2*)&outp[(size_t)row0 * G_DIM + col] =
                    make_float2(acc[mi][ni][0], acc[mi][ni][1]);
            if (row0 + 8 < N_NODES)
                *(float2*)&outp[(size_t)(row0 + 8) * G_DIM + col] =
                    make_float2(acc[mi][ni][2], acc[mi][ni][3]);
        }
    }
}

// ---------------- scan ----------------
__global__ __launch_bounds__(1024) void scan_phase1() {
    __shared__ int ws[32];
    int t = threadIdx.x;
    int lane = t & 31, wid = t >> 5;
    int idx = blockIdx.x * 1024 + t;
    int v = (idx < N_NODES) ? g_deg[idx] : 0;

    int x = v;
    #pragma unroll
    for (int o = 1; o < 32; o <<= 1) {
        int y = __shfl_up_sync(0xffffffffu, x, o);
        if (lane >= o) x += y;
    }
    if (lane == 31) ws[wid] = x;
    __syncthreads();
    if (wid == 0) {
        int w = ws[lane];
        #pragma unroll
        for (int o = 1; o < 32; o <<= 1) {
            int y = __shfl_up_sync(0xffffffffu, w, o);
            if (lane >= o) w += y;
        }
        ws[lane] = w;
    }
    __syncthreads();
    int ex = x - v + ((wid > 0) ? ws[wid - 1] : 0);
    if (idx < N_NODES) { g_off[idx] = ex; g_cur[idx] = 0; }
    if (t == 1023) g_bsum[blockIdx.x] = ex + v;
}

__global__ void scan_phase2() {
    int t = threadIdx.x;   // 32 threads
    int v = (t < 30) ? g_bsum[t] : 0;
    int x = v;
    #pragma unroll
    for (int o = 1; o < 32; o <<= 1) {
        int y = __shfl_up_sync(0xffffffffu, x, o);
        if (t >= o) x += y;
    }
    g_bsum[t] = x - v;
}

__global__ __launch_bounds__(1024) void scan_phase3() {
    int idx = blockIdx.x * 1024 + threadIdx.x;
    if (idx < N_NODES) g_off[idx] += g_bsum[blockIdx.x];
    if (idx == 0) g_off[N_NODES] = E_EDGES;
}

__global__ void scatter_kernel(const int* __restrict__ src, const int* __restrict__ dst) {
    int e = blockIdx.x * blockDim.x + threadIdx.x;
    if (e >= E_EDGES) return;
    int d = dst[e];
    int pos = atomicAdd(&g_cur[d], 1);
    g_csr_src[g_off[d] + pos] = src[e];
}

// ---------------- per-node attention: 64 threads (2 warps) per dst node ----------------
__device__ __forceinline__ float ex2f(float x) {
    float r;
    asm("ex2.approx.ftz.f32 %0, %1;" : "=f"(r) : "f"(x));
    return r;
}

__global__ __launch_bounds__(256) void attn_kernel(float* __restrict__ out) {
    int gtid = blockIdx.x * blockDim.x + threadIdx.x;
    int node = gtid >> 6;
    if (node >= N_NODES) return;
    int doff = gtid & 63;     // float4 index within the 256-dim row

    const float KS = ATT_SCALE * LOG2E;
    float4 kv = ((const float4*)(g_k + (size_t)node * G_DIM))[doff];
    kv.x *= KS; kv.y *= KS; kv.z *= KS; kv.w *= KS;

    float4 z = make_float4(0.f, 0.f, 0.f, 0.f);
    float4 a = make_float4(0.f, 0.f, 0.f, 0.f);

    int e   = g_off[node];
    int end = g_off[node + 1];

    for (; e + 4 <= end; e += 4) {
        int s0 = g_csr_src[e];
        int s1 = g_csr_src[e + 1];
        int s2 = g_csr_src[e + 2];
        int s3 = g_csr_src[e + 3];
        float4 q0 = ((const float4*)(g_q + (size_t)s0 * G_DIM))[doff];
        float4 v0 = ((const float4*)(g_v + (size_t)s0 * G_DIM))[doff];
        float4 q1 = ((const float4*)(g_q + (size_t)s1 * G_DIM))[doff];
        float4 v1 = ((const float4*)(g_v + (size_t)s1 * G_DIM))[doff];
        float4 q2 = ((const float4*)(g_q + (size_t)s2 * G_DIM))[doff];
        float4 v2 = ((const float4*)(g_v + (size_t)s2 * G_DIM))[doff];
        float4 q3 = ((const float4*)(g_q + (size_t)s3 * G_DIM))[doff];
        float4 v3 = ((const float4*)(g_v + (size_t)s3 * G_DIM))[doff];

        float p;
        p = ex2f(q0.x * kv.x); z.x += p; a.x = fmaf(p, v0.x, a.x);
        p = ex2f(q0.y * kv.y); z.y += p; a.y = fmaf(p, v0.y, a.y);
        p = ex2f(q0.z * kv.z); z.z += p; a.z = fmaf(p, v0.z, a.z);
        p = ex2f(q0.w * kv.w); z.w += p; a.w = fmaf(p, v0.w, a.w);
        p = ex2f(q1.x * kv.x); z.x += p; a.x = fmaf(p, v1.x, a.x);
        p = ex2f(q1.y * kv.y); z.y += p; a.y = fmaf(p, v1.y, a.y);
        p = ex2f(q1.z * kv.z); z.z += p; a.z = fmaf(p, v1.z, a.z);
        p = ex2f(q1.w * kv.w); z.w += p; a.w = fmaf(p, v1.w, a.w);
        p = ex2f(q2.x * kv.x); z.x += p; a.x = fmaf(p, v2.x, a.x);
        p = ex2f(q2.y * kv.y); z.y += p; a.y = fmaf(p, v2.y, a.y);
        p = ex2f(q2.z * kv.z); z.z += p; a.z = fmaf(p, v2.z, a.z);
        p = ex2f(q2.w * kv.w); z.w += p; a.w = fmaf(p, v2.w, a.w);
        p = ex2f(q3.x * kv.x); z.x += p; a.x = fmaf(p, v3.x, a.x);
        p = ex2f(q3.y * kv.y); z.y += p; a.y = fmaf(p, v3.y, a.y);
        p = ex2f(q3.z * kv.z); z.z += p; a.z = fmaf(p, v3.z, a.z);
        p = ex2f(q3.w * kv.w); z.w += p; a.w = fmaf(p, v3.w, a.w);
    }
    for (; e < end; e++) {
        int s0 = g_csr_src[e];
        float4 q0 = ((const float4*)(g_q + (size_t)s0 * G_DIM))[doff];
        float4 v0 = ((const float4*)(g_v + (size_t)s0 * G_DIM))[doff];
        float p;
        p = ex2f(q0.x * kv.x); z.x += p; a.x = fmaf(p, v0.x, a.x);
        p = ex2f(q0.y * kv.y); z.y += p; a.y = fmaf(p, v0.y, a.y);
        p = ex2f(q0.z * kv.z); z.z += p; a.z = fmaf(p, v0.z, a.z);
        p = ex2f(q0.w * kv.w); z.w += p; a.w = fmaf(p, v0.w, a.w);
    }

    float4 r;
    r.x = (z.x > 0.f) ? a.x / z.x : 0.f;
    r.y = (z.y > 0.f) ? a.y / z.y : 0.f;
    r.z = (z.z > 0.f) ? a.z / z.z : 0.f;
    r.w = (z.w > 0.f) ? a.w / z.w : 0.f;
    ((float4*)(out + (size_t)node * G_DIM))[doff] = r;
}

// ---------------- launch ----------------
// Order keeps the GEMM as the 4th launch (ncu -s capture window):
// zero_wconv(1), hist(2), ln(3), gemm(4), scan1(5), scan2(6), scan3(7), scatter(8), attn(9)
extern "C" void kernel_launch(void* const* d_in, const int* in_sizes, int n_in,
                              void* d_out, int out_size) {
    const float* s     = (const float*)d_in[0];
    const float* Wqkv  = (const float*)d_in[1];
    const float* gamma = (const float*)d_in[2];
    const float* beta  = (const float*)d_in[3];
    const int*   src   = (const int*)d_in[4];
    const int*   dst   = (const int*)d_in[5];
    float* out = (float*)d_out;

    static int smem_cfg_done = 0;
    if (!smem_cfg_done) {
        cudaFuncSetAttribute(qkv_gemm_tf32_kernel,
                             cudaFuncAttributeMaxDynamicSharedMemorySize,
                             GEMM_SMEM_BYTES);
        smem_cfg_done = 1;
    }

    zero_wconv_kernel<<<(W_VEC4 + 255) / 256, 256>>>(Wqkv);
    hist_kernel<<<(E_EDGES + 255) / 256, 256>>>(dst);
    ln_kernel<<<(N_NODES * 32 + 255) / 256, 256>>>(s, gamma, beta);

    dim3 gemm_grid(768 / 128, (N_NODES + 127) / 128);   // 6 x 235
    qkv_gemm_tf32_kernel<<<gemm_grid, 256, GEMM_SMEM_BYTES>>>();

    const int SCAN_BLOCKS = (N_NODES + 1023) / 1024;   // 30
    scan_phase1<<<SCAN_BLOCKS, 1024>>>();
    scan_phase2<<<1, 32>>>();
    scan_phase3<<<SCAN_BLOCKS, 1024>>>();

    scatter_kernel<<<(E_EDGES + 255) / 256, 256>>>(src, dst);

    attn_kernel<<<(N_NODES * 64 + 255) / 256, 256>>>(out);
}

// round 17
// speedup vs baseline: 2.1292x; 1.1030x over previous
#include <cuda_runtime.h>
#include <cuda_bf16.h>
#include <math.h>
#include <stdint.h>

#define N_NODES 30000
#define E_EDGES 480000
#define G_DIM   256
#define ATT_SCALE 0.0625f   /* 256^-0.5 */
#define LOG2E   1.4426950408889634f
#define LN_EPS  1e-5f

// natural-layout smem tiles; both A and B are [128 rows][36 words] (stride ≡4 mod 32)
#define T_ROW_STRIDE 36
#define T_BUF (128 * T_ROW_STRIDE)         /* 4608 words */
#define STAGE_WORDS (2 * T_BUF)            /* 9216 (A then B) */
#define N_STAGES 3
#define GEMM_SMEM_BYTES (N_STAGES * STAGE_WORDS * 4)    /* 110592 */

#define W_ELEMS (G_DIM * 768)              /* 196608 */

// ---------------- device scratch (static allocation only) ----------------
__device__ float    g_x[N_NODES * G_DIM];    // LN output, pre-rounded to tf32
__device__ uint32_t g_wt[W_ELEMS];           // W transposed [768 n][256 k], tf32 bits
__device__ uint32_t g_qh[N_NODES * G_DIM / 2];  // q in bf16 pairs
__device__ float    g_k[N_NODES * G_DIM];
__device__ float    g_v[N_NODES * G_DIM];
__device__ int      g_deg[N_NODES];
__device__ int      g_cur[N_NODES];
__device__ int      g_off[N_NODES + 1];
__device__ int      g_csr_src[E_EDGES];
__device__ int      g_bsum[32];

// ---------------- tf32 / async helpers ----------------
__device__ __forceinline__ uint32_t to_tf32(float x) {
    uint32_t t;
    asm("cvt.rna.tf32.f32 %0, %1;" : "=r"(t) : "f"(x));
    return t;
}

__device__ __forceinline__ void mma_tf32(float c[4], const uint32_t a[4], const uint32_t b[2]) {
    asm volatile(
        "mma.sync.aligned.m16n8k8.row.col.f32.tf32.tf32.f32 "
        "{%0,%1,%2,%3}, {%4,%5,%6,%7}, {%8,%9}, {%0,%1,%2,%3};"
        : "+f"(c[0]), "+f"(c[1]), "+f"(c[2]), "+f"(c[3])
        : "r"(a[0]), "r"(a[1]), "r"(a[2]), "r"(a[3]), "r"(b[0]), "r"(b[1]));
}

__device__ __forceinline__ void ldsm_x4(uint32_t& r0, uint32_t& r1, uint32_t& r2,
                                        uint32_t& r3, uint32_t saddr) {
    asm volatile("ldmatrix.sync.aligned.m8n8.x4.shared.b16 {%0,%1,%2,%3}, [%4];"
                 : "=r"(r0), "=r"(r1), "=r"(r2), "=r"(r3) : "r"(saddr));
}

__device__ __forceinline__ void cp_async16(uint32_t dst_sh, const void* src, int src_sz) {
    asm volatile("cp.async.cg.shared.global [%0], [%1], 16, %2;"
                 :: "r"(dst_sh), "l"(src), "r"(src_sz));
}
__device__ __forceinline__ void cp_commit() {
    asm volatile("cp.async.commit_group;");
}
template <int N>
__device__ __forceinline__ void cp_wait() {
    asm volatile("cp.async.wait_group %0;" :: "n"(N));
}

// ---------------- W transpose + tf32 pre-round + zero g_deg ----------------
// W [256 k][768 n] -> g_wt [768 n][256 k]; 32x32 smem tiles, 256 threads.
__global__ void wconv_kernel(const float* __restrict__ W) {
    __shared__ float t[32][33];
    int nb = blockIdx.x * 32;     // 24 tiles
    int kb = blockIdx.y * 32;     // 8 tiles
    int r = threadIdx.x >> 5;     // 0..7
    int c = threadIdx.x & 31;
    #pragma unroll
    for (int i = 0; i < 4; i++)
        t[r + 8 * i][c] = W[(size_t)(kb + r + 8 * i) * 768 + nb + c];
    __syncthreads();
    #pragma unroll
    for (int i = 0; i < 4; i++)
        g_wt[(size_t)(nb + r + 8 * i) * 256 + kb + c] = to_tf32(t[c][r + 8 * i]);

    int gid = (blockIdx.y * gridDim.x + blockIdx.x) * 256 + threadIdx.x;
    if (gid < N_NODES) g_deg[gid] = 0;
}

// ---------------- CSR histogram ----------------
__global__ void hist_kernel(const int* __restrict__ dst) {
    int e = blockIdx.x * blockDim.x + threadIdx.x;
    if (e < E_EDGES) atomicAdd(&g_deg[dst[e]], 1);
}

// ---------------- LayerNorm (stats + apply + tf32 round), one warp per row ----------------
__global__ void ln_kernel(const float* __restrict__ s,
                          const float* __restrict__ gamma,
                          const float* __restrict__ beta) {
    int gtid = blockIdx.x * blockDim.x + threadIdx.x;
    int row = gtid >> 5;
    if (row >= N_NODES) return;
    int lane = threadIdx.x & 31;

    const float4* p = (const float4*)(s + (size_t)row * G_DIM);
    float4 f0 = p[lane];
    float4 f1 = p[lane + 32];
    float sum = f0.x + f0.y + f0.z + f0.w + f1.x + f1.y + f1.z + f1.w;
    float sq  = f0.x*f0.x + f0.y*f0.y + f0.z*f0.z + f0.w*f0.w
              + f1.x*f1.x + f1.y*f1.y + f1.z*f1.z + f1.w*f1.w;
    #pragma unroll
    for (int o = 16; o > 0; o >>= 1) {
        sum += __shfl_xor_sync(0xffffffffu, sum, o);
        sq  += __shfl_xor_sync(0xffffffffu, sq, o);
    }
    float mu = sum * (1.f / G_DIM);
    float rs = rsqrtf(sq * (1.f / G_DIM) - mu * mu + LN_EPS);

    float4 ga = ((const float4*)gamma)[lane];
    float4 gb = ((const float4*)gamma)[lane + 32];
    float4 ba = ((const float4*)beta)[lane];
    float4 bb = ((const float4*)beta)[lane + 32];
    float4 o0, o1;
    o0.x = __uint_as_float(to_tf32((f0.x - mu) * rs * ga.x + ba.x));
    o0.y = __uint_as_float(to_tf32((f0.y - mu) * rs * ga.y + ba.y));
    o0.z = __uint_as_float(to_tf32((f0.z - mu) * rs * ga.z + ba.z));
    o0.w = __uint_as_float(to_tf32((f0.w - mu) * rs * ga.w + ba.w));
    o1.x = __uint_as_float(to_tf32((f1.x - mu) * rs * gb.x + bb.x));
    o1.y = __uint_as_float(to_tf32((f1.y - mu) * rs * gb.y + bb.y));
    o1.z = __uint_as_float(to_tf32((f1.z - mu) * rs * gb.z + bb.z));
    o1.w = __uint_as_float(to_tf32((f1.w - mu) * rs * gb.w + bb.w));
    float4* op = (float4*)(g_x + (size_t)row * G_DIM);
    op[lane]      = o0;
    op[lane + 32] = o1;
}

// ---------------- QKV GEMM (tf32, 128x128 tile, 3-stage ring, full-ldmatrix) -------
// C[N,768] = X[N,256] @ Wt[768,256]^T; 8 warps (4M x 2N), warp tile 32x64.
// Both A and B tiles are [128][36]; fragments via ldmatrix.x4 only.
__global__ __launch_bounds__(256, 2) void qkv_gemm_tf32_kernel() {

    extern __shared__ uint32_t smem[];

    int tid  = threadIdx.x;
    int warp = tid >> 5;
    int lane = tid & 31;
    int wm = warp >> 1;          // 0..3 (M)
    int wn = warp & 1;           // 0..1 (N)
    int bm = blockIdx.y * 128;
    int bn = blockIdx.x * 128;

    float acc[2][8][4];
    #pragma unroll
    for (int mi = 0; mi < 2; mi++)
        #pragma unroll
        for (int ni = 0; ni < 8; ni++)
            #pragma unroll
            for (int r = 0; r < 4; r++) acc[mi][ni][r] = 0.f;

    // staging coordinates (A and B identical structure)
    int tr[4], tc4[4], t_st[4], asz[4];
    #pragma unroll
    for (int i = 0; i < 4; i++) {
        int idx = tid + i * 256;
        tr[i]  = idx >> 3;            // 0..127
        tc4[i] = (idx & 7) * 4;       // 0..28
        t_st[i] = tr[i] * T_ROW_STRIDE + tc4[i];
        asz[i] = (bm + tr[i] < N_NODES) ? 16 : 0;
    }
    const float* a_src[4];
    const uint32_t* b_src[4];
    #pragma unroll
    for (int i = 0; i < 4; i++) {
        int gr = bm + tr[i];
        if (gr >= N_NODES) gr = N_NODES - 1;
        a_src[i] = g_x + (size_t)gr * G_DIM + tc4[i];
        b_src[i] = g_wt + (size_t)(bn + tr[i]) * 256 + tc4[i];
    }

    uint32_t smem_sh = (uint32_t)__cvta_generic_to_shared(smem);

    // ldmatrix per-lane addresses: x4 tiles (r,c)(r+8,c)(r,c+4)(r+8,c+4)
    int lr = lane & 7, tile = lane >> 3;
    uint32_t a_sm0 = smem_sh +
        (uint32_t)((wm * 32 + (tile & 1) * 8 + lr) * T_ROW_STRIDE) * 4u +
        (uint32_t)(tile >> 1) * 16u;
    // B: x4 tiles (n8a,klo)(n8a,khi)(n8b,klo)(n8b,khi)
    uint32_t b_sm0 = smem_sh + (uint32_t)T_BUF * 4u +
        (uint32_t)((wn * 64 + (tile >> 1) * 8 + lr) * T_ROW_STRIDE) * 4u +
        (uint32_t)(tile & 1) * 16u;

    // ---- prologue: async-stage K-tiles 0 and 1 into stages 0, 1
    #pragma unroll
    for (int st = 0; st < 2; st++) {
        uint32_t base = smem_sh + (uint32_t)(st * STAGE_WORDS) * 4u;
        int kt = st * 32;
        #pragma unroll
        for (int i = 0; i < 4; i++)
            cp_async16(base + (uint32_t)t_st[i] * 4u, a_src[i] + kt, asz[i]);
        #pragma unroll
        for (int i = 0; i < 4; i++)
            cp_async16(base + (uint32_t)(T_BUF + t_st[i]) * 4u, b_src[i] + kt, 16);
        cp_commit();
    }

    int cur = 0;
    for (int kt8 = 0; kt8 < 8; kt8++) {
        if (kt8 < 7) cp_wait<1>(); else cp_wait<0>();
        __syncthreads();

        uint32_t stage_off = (uint32_t)(cur * STAGE_WORDS) * 4u;
        uint32_t a_base = a_sm0 + stage_off;
        uint32_t b_base = b_sm0 + stage_off;

        #pragma unroll
        for (int ks = 0; ks < 4; ks++) {
            uint32_t a[2][4];
            #pragma unroll
            for (int mi = 0; mi < 2; mi++)
                ldsm_x4(a[mi][0], a[mi][1], a[mi][2], a[mi][3],
                        a_base + (uint32_t)(mi * 16 * T_ROW_STRIDE) * 4u + (uint32_t)ks * 32u);
            uint32_t b[8][2];
            #pragma unroll
            for (int ni2 = 0; ni2 < 4; ni2++) {
                uint32_t r0, r1, r2, r3;
                ldsm_x4(r0, r1, r2, r3,
                        b_base + (uint32_t)(ni2 * 16 * T_ROW_STRIDE) * 4u + (uint32_t)ks * 32u);
                b[ni2 * 2][0] = r0;     b[ni2 * 2][1] = r1;
                b[ni2 * 2 + 1][0] = r2; b[ni2 * 2 + 1][1] = r3;
            }
            #pragma unroll
            for (int mi = 0; mi < 2; mi++)
                #pragma unroll
                for (int ni = 0; ni < 8; ni++)
                    mma_tf32(acc[mi][ni], a[mi], b[ni]);
        }

        if (kt8 < 6) {
            int kt = (kt8 + 2) * 32;
            int nst = cur + 2; if (nst >= N_STAGES) nst -= N_STAGES;
            uint32_t base = smem_sh + (uint32_t)(nst * STAGE_WORDS) * 4u;
            #pragma unroll
            for (int i = 0; i < 4; i++)
                cp_async16(base + (uint32_t)t_st[i] * 4u, a_src[i] + kt, asz[i]);
            #pragma unroll
            for (int i = 0; i < 4; i++)
                cp_async16(base + (uint32_t)(T_BUF + t_st[i]) * 4u, b_src[i] + kt, 16);
            cp_commit();
        }
        if (++cur == N_STAGES) cur = 0;
    }

    // ---- epilogue: q third -> bf16 pairs; k/v thirds -> fp32
    int third = bn >> 8;
    int lc_base = (bn & 255) + wn * 64;
    int gid = lane >> 2, tig = lane & 3;
    if (third == 0) {
        #pragma unroll
        for (int mi = 0; mi < 2; mi++) {
            int row0 = bm + wm * 32 + mi * 16 + gid;
            #pragma unroll
            for (int ni = 0; ni < 8; ni++) {
                int col = lc_base + ni * 8 + tig * 2;
                if (row0 < N_NODES) {
                    __nv_bfloat162 h = __float22bfloat162_rn(
                        make_float2(acc[mi][ni][0], acc[mi][ni][1]));
                    g_qh[row0 * 128 + (col >> 1)] = *(uint32_t*)&h;
                }
                if (row0 + 8 < N_NODES) {
                    __nv_bfloat162 h = __float22bfloat162_rn(
                        make_float2(acc[mi][ni][2], acc[mi][ni][3]));
                    g_qh[(row0 + 8) * 128 + (col >> 1)] = *(uint32_t*)&h;
                }
            }
        }
    } else {
        float* outp = (third == 1) ? g_k : g_v;
        #pragma unroll
        for (int mi = 0; mi < 2; mi++) {
            int row0 = bm + wm * 32 + mi * 16 + gid;
            #pragma unroll
            for (int ni = 0; ni < 8; ni++) {
                int col = lc_base + ni * 8 + tig * 2;
                if (row0 < N_NODES)
                    *(float2*)&outp[(size_t)row0 * G_DIM + col] =
                        make_float2(acc[mi][ni][0], acc[mi][ni][1]);
                if (row0 + 8 < N_NODES)
                    *(float2*)&outp[(size_t)(row0 + 8) * G_DIM + col] =
                        make_float2(acc[mi][ni][2], acc[mi][ni][3]);
            }
        }
    }
}

// ---------------- scan ----------------
__global__ __launch_bounds__(1024) void scan_phase1() {
    __shared__ int ws[32];
    int t = threadIdx.x;
    int lane = t & 31, wid = t >> 5;
    int idx = blockIdx.x * 1024 + t;
    int v = (idx < N_NODES) ? g_deg[idx] : 0;

    int x = v;
    #pragma unroll
    for (int o = 1; o < 32; o <<= 1) {
        int y = __shfl_up_sync(0xffffffffu, x, o);
        if (lane >= o) x += y;
    }
    if (lane == 31) ws[wid] = x;
    __syncthreads();
    if (wid == 0) {
        int w = ws[lane];
        #pragma unroll
        for (int o = 1; o < 32; o <<= 1) {
            int y = __shfl_up_sync(0xffffffffu, w, o);
            if (lane >= o) w += y;
        }
        ws[lane] = w;
    }
    __syncthreads();
    int ex = x - v + ((wid > 0) ? ws[wid - 1] : 0);
    if (idx < N_NODES) { g_off[idx] = ex; g_cur[idx] = 0; }
    if (t == 1023) g_bsum[blockIdx.x] = ex + v;
}

__global__ void scan_phase2() {
    int t = threadIdx.x;   // 32 threads
    int v = (t < 30) ? g_bsum[t] : 0;
    int x = v;
    #pragma unroll
    for (int o = 1; o < 32; o <<= 1) {
        int y = __shfl_up_sync(0xffffffffu, x, o);
        if (t >= o) x += y;
    }
    g_bsum[t] = x - v;
}

__global__ __launch_bounds__(1024) void scan_phase3() {
    int idx = blockIdx.x * 1024 + threadIdx.x;
    if (idx < N_NODES) g_off[idx] += g_bsum[blockIdx.x];
    if (idx == 0) g_off[N_NODES] = E_EDGES;
}

__global__ void scatter_kernel(const int* __restrict__ src, const int* __restrict__ dst) {
    int e = blockIdx.x * blockDim.x + threadIdx.x;
    if (e >= E_EDGES) return;
    int d = dst[e];
    int pos = atomicAdd(&g_cur[d], 1);
    g_csr_src[g_off[d] + pos] = src[e];
}

// ---------------- per-node attention: 64 threads (2 warps) per dst node ----------------
__device__ __forceinline__ float ex2f(float x) {
    float r;
    asm("ex2.approx.ftz.f32 %0, %1;" : "=f"(r) : "f"(x));
    return r;
}

__device__ __forceinline__ float4 qh_to_float4(uint2 qw) {
    float2 lo = __bfloat1622float2(*(__nv_bfloat162*)&qw.x);
    float2 hi = __bfloat1622float2(*(__nv_bfloat162*)&qw.y);
    return make_float4(lo.x, lo.y, hi.x, hi.y);
}

__global__ __launch_bounds__(256) void attn_kernel(float* __restrict__ out) {
    int gtid = blockIdx.x * blockDim.x + threadIdx.x;
    int node = gtid >> 6;
    if (node >= N_NODES) return;
    int doff = gtid & 63;     // float4 index within the 256-dim row

    const float KS = ATT_SCALE * LOG2E;
    float4 kv = ((const float4*)(g_k + (size_t)node * G_DIM))[doff];
    kv.x *= KS; kv.y *= KS; kv.z *= KS; kv.w *= KS;

    float4 z = make_float4(0.f, 0.f, 0.f, 0.f);
    float4 a = make_float4(0.f, 0.f, 0.f, 0.f);

    int e   = g_off[node];
    int end = g_off[node + 1];

    for (; e + 4 <= end; e += 4) {
        int s0 = g_csr_src[e];
        int s1 = g_csr_src[e + 1];
        int s2 = g_csr_src[e + 2];
        int s3 = g_csr_src[e + 3];
        uint2 qw0 = ((const uint2*)g_qh)[s0 * 64 + doff];
        float4 v0 = ((const float4*)(g_v + (size_t)s0 * G_DIM))[doff];
        uint2 qw1 = ((const uint2*)g_qh)[s1 * 64 + doff];
        float4 v1 = ((const float4*)(g_v + (size_t)s1 * G_DIM))[doff];
        uint2 qw2 = ((const uint2*)g_qh)[s2 * 64 + doff];
        float4 v2 = ((const float4*)(g_v + (size_t)s2 * G_DIM))[doff];
        uint2 qw3 = ((const uint2*)g_qh)[s3 * 64 + doff];
        float4 v3 = ((const float4*)(g_v + (size_t)s3 * G_DIM))[doff];
        float4 q0 = qh_to_float4(qw0);
        float4 q1 = qh_to_float4(qw1);
        float4 q2 = qh_to_float4(qw2);
        float4 q3 = qh_to_float4(qw3);

        float p;
        p = ex2f(q0.x * kv.x); z.x += p; a.x = fmaf(p, v0.x, a.x);
        p = ex2f(q0.y * kv.y); z.y += p; a.y = fmaf(p, v0.y, a.y);
        p = ex2f(q0.z * kv.z); z.z += p; a.z = fmaf(p, v0.z, a.z);
        p = ex2f(q0.w * kv.w); z.w += p; a.w = fmaf(p, v0.w, a.w);
        p = ex2f(q1.x * kv.x); z.x += p; a.x = fmaf(p, v1.x, a.x);
        p = ex2f(q1.y * kv.y); z.y += p; a.y = fmaf(p, v1.y, a.y);
        p = ex2f(q1.z * kv.z); z.z += p; a.z = fmaf(p, v1.z, a.z);
        p = ex2f(q1.w * kv.w); z.w += p; a.w = fmaf(p, v1.w, a.w);
        p = ex2f(q2.x * kv.x); z.x += p; a.x = fmaf(p, v2.x, a.x);
        p = ex2f(q2.y * kv.y); z.y += p; a.y = fmaf(p, v2.y, a.y);
        p = ex2f(q2.z * kv.z); z.z += p; a.z = fmaf(p, v2.z, a.z);
        p = ex2f(q2.w * kv.w); z.w += p; a.w = fmaf(p, v2.w, a.w);
        p = ex2f(q3.x * kv.x); z.x += p; a.x = fmaf(p, v3.x, a.x);
        p = ex2f(q3.y * kv.y); z.y += p; a.y = fmaf(p, v3.y, a.y);
        p = ex2f(q3.z * kv.z); z.z += p; a.z = fmaf(p, v3.z, a.z);
        p = ex2f(q3.w * kv.w); z.w += p; a.w = fmaf(p, v3.w, a.w);
    }
    for (; e < end; e++) {
        int s0 = g_csr_src[e];
        float4 q0 = qh_to_float4(((const uint2*)g_qh)[s0 * 64 + doff]);
        float4 v0 = ((const float4*)(g_v + (size_t)s0 * G_DIM))[doff];
        float p;
        p = ex2f(q0.x * kv.x); z.x += p; a.x = fmaf(p, v0.x, a.x);
        p = ex2f(q0.y * kv.y); z.y += p; a.y = fmaf(p, v0.y, a.y);
        p = ex2f(q0.z * kv.z); z.z += p; a.z = fmaf(p, v0.z, a.z);
        p = ex2f(q0.w * kv.w); z.w += p; a.w = fmaf(p, v0.w, a.w);
    }

    float4 r;
    r.x = (z.x > 0.f) ? a.x / z.x : 0.f;
    r.y = (z.y > 0.f) ? a.y / z.y : 0.f;
    r.z = (z.z > 0.f) ? a.z / z.z : 0.f;
    r.w = (z.w > 0.f) ? a.w / z.w : 0.f;
    ((float4*)(out + (size_t)node * G_DIM))[doff] = r;
}

// ---------------- launch ----------------
// Order keeps the GEMM as the 4th launch (ncu -s capture window):
// wconv(1), hist(2), ln(3), gemm(4), scan1(5), scan2(6), scan3(7), scatter(8), attn(9)
extern "C" void kernel_launch(void* const* d_in, const int* in_sizes, int n_in,
                              void* d_out, int out_size) {
    const float* s     = (const float*)d_in[0];
    const float* Wqkv  = (const float*)d_in[1];
    const float* gamma = (const float*)d_in[2];
    const float* beta  = (const float*)d_in[3];
    const int*   src   = (const int*)d_in[4];
    const int*   dst   = (const int*)d_in[5];
    float* out = (float*)d_out;

    static int smem_cfg_done = 0;
    if (!smem_cfg_done) {
        cudaFuncSetAttribute(qkv_gemm_tf32_kernel,
                             cudaFuncAttributeMaxDynamicSharedMemorySize,
                             GEMM_SMEM_BYTES);
        smem_cfg_done = 1;
    }

    dim3 wgrid(768 / 32, 256 / 32);   // 24 x 8
    wconv_kernel<<<wgrid, 256>>>(Wqkv);
    hist_kernel<<<(E_EDGES + 255) / 256, 256>>>(dst);
    ln_kernel<<<(N_NODES * 32 + 255) / 256, 256>>>(s, gamma, beta);

    dim3 gemm_grid(768 / 128, (N_NODES + 127) / 128);   // 6 x 235
    qkv_gemm_tf32_kernel<<<gemm_grid, 256, GEMM_SMEM_BYTES>>>();

    const int SCAN_BLOCKS = (N_NODES + 1023) / 1024;   // 30
    scan_phase1<<<SCAN_BLOCKS, 1024>>>();
    scan_phase2<<<1, 32>>>();
    scan_phase3<<<SCAN_BLOCKS, 1024>>>();

    scatter_kernel<<<(E_EDGES + 255) / 256, 256>>>(src, dst);

    attn_kernel<<<(N_NODES * 64 + 255) / 256, 256>>>(out);
}